// round 8
// baseline (speedup 1.0000x reference)
#include <cuda_runtime.h>
#include <cuda_bf16.h>
#include <math.h>
#include <stdint.h>

// Problem constants
constexpr int Bb = 2, Ss = 2048, Dd = 1024, Hh = 16, DH = 64;
constexpr int MM = Bb * Ss;       // 4096 rows

// ---------------- scratch (no cudaMalloc allowed) ----------------
__device__ __nv_bfloat16 g_xhi[MM * Dd];
__device__ __nv_bfloat16 g_xlo[MM * Dd];
__device__ __nv_bfloat16 g_qhi[MM * Dd];
__device__ __nv_bfloat16 g_qlo[MM * Dd];
__device__ __nv_bfloat16 g_khi[MM * Dd];
__device__ __nv_bfloat16 g_klo[MM * Dd];
__device__ __nv_bfloat16 g_vhi[MM * Dd];
__device__ __nv_bfloat16 g_vlo[MM * Dd];
__device__ __nv_bfloat16 g_ahi[MM * Dd];
__device__ __nv_bfloat16 g_alo[MM * Dd];
__device__ __nv_bfloat16 g_wthi[4 * Dd * Dd];    // transposed weights [N,K], Wq|Wk|Wv|Wo
__device__ __nv_bfloat16 g_wtlo[4 * Dd * Dd];

// ================= helpers =================
__device__ __forceinline__ uint32_t smem_u32(const void* p) {
    uint32_t a;
    asm("{ .reg .u64 t; cvta.to.shared.u64 t, %1; cvt.u32.u64 %0, t; }" : "=r"(a) : "l"(p));
    return a;
}
__device__ __forceinline__ void ldsm_x4(uint32_t* r, uint32_t a) {
    asm volatile("ldmatrix.sync.aligned.m8n8.x4.shared.b16 {%0,%1,%2,%3}, [%4];"
                 : "=r"(r[0]), "=r"(r[1]), "=r"(r[2]), "=r"(r[3]) : "r"(a));
}
__device__ __forceinline__ void ldsm_x4_t(uint32_t* r, uint32_t a) {
    asm volatile("ldmatrix.sync.aligned.m8n8.x4.trans.shared.b16 {%0,%1,%2,%3}, [%4];"
                 : "=r"(r[0]), "=r"(r[1]), "=r"(r[2]), "=r"(r[3]) : "r"(a));
}
__device__ __forceinline__ void mma_bf16(float* c, const uint32_t* a, const uint32_t* b) {
    asm volatile("mma.sync.aligned.m16n8k16.row.col.f32.bf16.bf16.f32 "
                 "{%0,%1,%2,%3}, {%4,%5,%6,%7}, {%8,%9}, {%0,%1,%2,%3};"
                 : "+f"(c[0]), "+f"(c[1]), "+f"(c[2]), "+f"(c[3])
                 : "r"(a[0]), "r"(a[1]), "r"(a[2]), "r"(a[3]), "r"(b[0]), "r"(b[1]));
}
__device__ __forceinline__ void cp16(uint32_t dst, const void* src) {
    asm volatile("cp.async.cg.shared.global [%0], [%1], 16;" :: "r"(dst), "l"(src));
}
#define CP_COMMIT() asm volatile("cp.async.commit_group;" ::: "memory")
#define CP_WAIT(n)  asm volatile("cp.async.wait_group %0;" :: "n"(n) : "memory")
#define SWZ128(off) ((off) ^ (((off) >> 3) & 0x70))

__device__ __forceinline__ void split1(float x, __nv_bfloat16& h, __nv_bfloat16& l) {
    h = __float2bfloat16(x);
    l = __float2bfloat16(x - __bfloat162float(h));
}
__device__ __forceinline__ uint32_t pkbf(__nv_bfloat16 a, __nv_bfloat16 b) {
    uint16_t ua = *(uint16_t*)&a, ub = *(uint16_t*)&b;
    return (uint32_t)ua | ((uint32_t)ub << 16);
}

// ================= split kernels =================
__global__ __launch_bounds__(256) void split_f32(
    const float* __restrict__ in, __nv_bfloat16* __restrict__ hi,
    __nv_bfloat16* __restrict__ lo)
{
    int i = blockIdx.x * 256 + threadIdx.x;
    float4 v = ((const float4*)in)[i];
    __nv_bfloat16 h0, h1, h2, h3, l0, l1, l2, l3;
    split1(v.x, h0, l0); split1(v.y, h1, l1); split1(v.z, h2, l2); split1(v.w, h3, l3);
    uint2 hp, lp;
    hp.x = pkbf(h0, h1); hp.y = pkbf(h2, h3);
    lp.x = pkbf(l0, l1); lp.y = pkbf(l2, l3);
    ((uint2*)hi)[i] = hp;
    ((uint2*)lo)[i] = lp;
}

// transpose W [K,N] -> Wt [N,K] bf16 hi/lo, for 4 weights (blockIdx.z)
__global__ __launch_bounds__(256) void transpose_split(
    const float* __restrict__ W0, const float* __restrict__ W1,
    const float* __restrict__ W2, const float* __restrict__ W3,
    __nv_bfloat16* __restrict__ hi, __nv_bfloat16* __restrict__ lo)
{
    __shared__ float sm[32][33];
    const float* W = (blockIdx.z == 0) ? W0 : (blockIdx.z == 1) ? W1 : (blockIdx.z == 2) ? W2 : W3;
    const int tx = threadIdx.x, ty = threadIdx.y;
    const int k0 = blockIdx.y * 32, n0 = blockIdx.x * 32;
#pragma unroll
    for (int i = 0; i < 4; i++)
        sm[ty + 8 * i][tx] = W[(size_t)(k0 + ty + 8 * i) * Dd + n0 + tx];
    __syncthreads();
    size_t zb = (size_t)blockIdx.z * Dd * Dd;
#pragma unroll
    for (int i = 0; i < 4; i++) {
        float v = sm[tx][ty + 8 * i];
        __nv_bfloat16 h, l; split1(v, h, l);
        size_t o = zb + (size_t)(n0 + ty + 8 * i) * Dd + k0 + tx;
        hi[o] = h; lo[o] = l;
    }
}

// ================= mma.sync GEMM (256 threads, known-good config) =================
constexpr int BM = 128, BN = 128, BKC = 64;
constexpr int STG_BYTES = 65536;
constexpr int OFF_AHI = 0, OFF_ALO = 16384, OFF_BHI = 32768, OFF_BLO = 49152;
constexpr int GEMM_SMEM = 2 * STG_BYTES + 1024;

template<int MODE>
__global__ __launch_bounds__(256, 1) void gemm_mma(
    const float* __restrict__ bias0, const float* __restrict__ bias1,
    const float* __restrict__ bias2, float* __restrict__ C)
{
    extern __shared__ char smc[];
    uint32_t sraw = smem_u32(smc);
    uint32_t sb = (sraw + 1023u) & ~1023u;

    const int tid = threadIdx.x, lid = tid & 31, wid = tid >> 5;
    const int wm = wid >> 2, wn = wid & 3;
    const int m0 = blockIdx.y * BM;
    const int z = (MODE == 0) ? (blockIdx.x >> 3) : 3;
    const int n0 = (MODE == 0) ? ((blockIdx.x & 7) * BN) : (blockIdx.x * BN);

    const __nv_bfloat16* Ahi = (MODE == 0) ? g_xhi : g_ahi;
    const __nv_bfloat16* Alo = (MODE == 0) ? g_xlo : g_alo;
    const __nv_bfloat16* Bhi = g_wthi + (size_t)z * Dd * Dd;
    const __nv_bfloat16* Blo = g_wtlo + (size_t)z * Dd * Dd;
    const float* bias = (MODE == 1) ? bias0 : ((z == 0) ? bias0 : (z == 1) ? bias1 : bias2);
    __nv_bfloat16* Chi = nullptr;
    __nv_bfloat16* Clo = nullptr;
    if (MODE == 0) {
        Chi = (z == 0) ? g_qhi : (z == 1) ? g_khi : g_vhi;
        Clo = (z == 0) ? g_qlo : (z == 1) ? g_klo : g_vlo;
    }

    uint32_t dsto[4];
    int rowA[4], rowB[4];
    uint32_t coff[4];
#pragma unroll
    for (int i = 0; i < 4; i++) {
        int idx = tid + i * 256;
        int r = idx >> 3;
        uint32_t off = (uint32_t)(r * 128 + (idx & 7) * 16);
        dsto[i] = SWZ128(off);
        rowA[i] = m0 + r;
        rowB[i] = n0 + r;
        coff[i] = (uint32_t)((idx & 7) * 16);
    }

    auto prefetch = [&](int chunk, int s) {
        uint32_t st = sb + s * STG_BYTES;
        size_t kb = (size_t)chunk * BKC * 2;
#pragma unroll
        for (int i = 0; i < 4; i++) {
            size_t ga = (size_t)rowA[i] * (Dd * 2) + kb + coff[i];
            size_t gb = (size_t)rowB[i] * (Dd * 2) + kb + coff[i];
            cp16(st + OFF_AHI + dsto[i], (const char*)Ahi + ga);
            cp16(st + OFF_ALO + dsto[i], (const char*)Alo + ga);
            cp16(st + OFF_BHI + dsto[i], (const char*)Bhi + gb);
            cp16(st + OFF_BLO + dsto[i], (const char*)Blo + gb);
        }
    };

    float acc[4][4][4];
#pragma unroll
    for (int mt = 0; mt < 4; mt++)
#pragma unroll
        for (int nt = 0; nt < 4; nt++)
#pragma unroll
            for (int e = 0; e < 4; e++) acc[mt][nt][e] = 0.f;

    prefetch(0, 0);
    CP_COMMIT();

    const int a_row = wm * 64 + (lid & 15);
    const uint32_t a_cb = (uint32_t)(((lid >> 4) & 1) * 16);
    const int mg = lid >> 3;
    const int b_row0 = wn * 32 + (mg >> 1) * 8 + (lid & 7);
    const uint32_t b_cb = (uint32_t)((mg & 1) * 16);

    const int NIT = Dd / BKC;   // 16
    for (int it = 0; it < NIT; it++) {
        const int s = it & 1;
        if (it + 1 < NIT) {
            prefetch(it + 1, (it + 1) & 1);
            CP_COMMIT();
            CP_WAIT(1);
        } else {
            CP_WAIT(0);
        }
        __syncthreads();

        uint32_t st = sb + s * STG_BYTES;
#pragma unroll
        for (int kt = 0; kt < 4; kt++) {
            uint32_t ah[4][4], al[4][4];
#pragma unroll
            for (int mt = 0; mt < 4; mt++) {
                uint32_t off = (uint32_t)((a_row + mt * 16) * 128) + kt * 32 + a_cb;
                off = SWZ128(off);
                ldsm_x4(ah[mt], st + OFF_AHI + off);
                ldsm_x4(al[mt], st + OFF_ALO + off);
            }
            uint32_t bh[4][2], bl[4][2];
#pragma unroll
            for (int p = 0; p < 2; p++) {
                uint32_t off = (uint32_t)((b_row0 + p * 16) * 128) + kt * 32 + b_cb;
                off = SWZ128(off);
                uint32_t r[4];
                ldsm_x4(r, st + OFF_BHI + off);
                bh[2 * p][0] = r[0]; bh[2 * p][1] = r[1];
                bh[2 * p + 1][0] = r[2]; bh[2 * p + 1][1] = r[3];
                ldsm_x4(r, st + OFF_BLO + off);
                bl[2 * p][0] = r[0]; bl[2 * p][1] = r[1];
                bl[2 * p + 1][0] = r[2]; bl[2 * p + 1][1] = r[3];
            }
#pragma unroll
            for (int mt = 0; mt < 4; mt++)
#pragma unroll
                for (int nt = 0; nt < 4; nt++) {
                    mma_bf16(acc[mt][nt], ah[mt], bh[nt]);
                    mma_bf16(acc[mt][nt], ah[mt], bl[nt]);
                    mma_bf16(acc[mt][nt], al[mt], bh[nt]);
                }
        }
        __syncthreads();
    }

    // epilogue
#pragma unroll
    for (int nt = 0; nt < 4; nt++) {
        int c0 = n0 + wn * 32 + nt * 8 + (lid & 3) * 2;
        float b0 = bias[c0], b1 = bias[c0 + 1];
#pragma unroll
        for (int mt = 0; mt < 4; mt++) {
            int r0 = m0 + wm * 64 + mt * 16 + (lid >> 2);
            float v0 = acc[mt][nt][0] + b0, v1 = acc[mt][nt][1] + b1;
            float v2 = acc[mt][nt][2] + b0, v3 = acc[mt][nt][3] + b1;
            if (MODE == 0) {
                __nv_bfloat16 h0, h1, h2, h3, l0, l1, l2, l3;
                split1(v0, h0, l0); split1(v1, h1, l1);
                split1(v2, h2, l2); split1(v3, h3, l3);
                *(uint32_t*)&Chi[(size_t)r0 * Dd + c0] = pkbf(h0, h1);
                *(uint32_t*)&Clo[(size_t)r0 * Dd + c0] = pkbf(l0, l1);
                *(uint32_t*)&Chi[(size_t)(r0 + 8) * Dd + c0] = pkbf(h2, h3);
                *(uint32_t*)&Clo[(size_t)(r0 + 8) * Dd + c0] = pkbf(l2, l3);
            } else {
                float2 w0 = {v0, v1}, w1 = {v2, v3};
                *(float2*)&C[(size_t)r0 * Dd + c0] = w0;
                *(float2*)&C[(size_t)(r0 + 8) * Dd + c0] = w1;
            }
        }
    }
}

// ================= Flash attention, software-pipelined across tiles =================
// Per iteration: QK(t+1) MMAs issue first (tensor pipe), softmax(t) runs on
// ALU/MUFU concurrently, then PV(t). ql evicted from regs (reloaded via LDSM).
constexpr int AT_STG = 32768;                      // Khi|Klo|Vhi|Vlo 8KB each
constexpr int A_QZ = 3 * AT_STG;                   // Q hi 16K + lo 16K (reused for out staging)
constexpr int ATT_SMEM = A_QZ + 32768 + 1024;
constexpr float SCL = 0.03125f;                    // 1/sqrt(1024)

// S = Q K^T (3-term); ql reloaded from smem per dim-chunk
__device__ __forceinline__ void qk_tile(
    uint32_t st, uint32_t qz, int a_row, uint32_t a_cb,
    int krow, uint32_t kcb, const uint32_t (&qh)[4][4], float (&s)[8][4])
{
#pragma unroll
    for (int nt = 0; nt < 8; nt++)
#pragma unroll
        for (int e = 0; e < 4; e++) s[nt][e] = 0.f;
#pragma unroll
    for (int kd = 0; kd < 4; kd++) {
        uint32_t ql_[4];
        ldsm_x4(ql_, qz + 16384 + SWZ128((uint32_t)(a_row * 128) + kd * 32 + a_cb));
#pragma unroll
        for (int np = 0; np < 4; np++) {
            uint32_t off = SWZ128((uint32_t)((np * 16 + krow) * 128) + kd * 32 + kcb);
            uint32_t bh_[4], bl_[4];
            ldsm_x4(bh_, st + 0 + off);        // Khi
            ldsm_x4(bl_, st + 8192 + off);     // Klo
            mma_bf16(s[2 * np],     qh[kd], bh_);
            mma_bf16(s[2 * np],     qh[kd], bl_);
            mma_bf16(s[2 * np],     ql_,    bh_);
            mma_bf16(s[2 * np + 1], qh[kd], bh_ + 2);
            mma_bf16(s[2 * np + 1], qh[kd], bl_ + 2);
            mma_bf16(s[2 * np + 1], ql_,    bh_ + 2);
        }
    }
}

template<bool MASK>
__device__ __forceinline__ void softmax_tile(
    float (&s)[8][4], int kv0, int r0g, int r1g, int lid,
    uint32_t (&pah)[4][4], uint32_t (&pal)[4][4],
    float (&o)[8][4], float& m0v, float& m1v, float& lsum0, float& lsum1)
{
    float tm0 = -INFINITY, tm1 = -INFINITY;
#pragma unroll
    for (int nt = 0; nt < 8; nt++) {
        if (MASK) {
            int kg = kv0 + nt * 8 + (lid & 3) * 2;
            s[nt][0] = (kg     <= r0g) ? s[nt][0] * SCL : -INFINITY;
            s[nt][1] = (kg + 1 <= r0g) ? s[nt][1] * SCL : -INFINITY;
            s[nt][2] = (kg     <= r1g) ? s[nt][2] * SCL : -INFINITY;
            s[nt][3] = (kg + 1 <= r1g) ? s[nt][3] * SCL : -INFINITY;
        } else {
            s[nt][0] *= SCL; s[nt][1] *= SCL;
            s[nt][2] *= SCL; s[nt][3] *= SCL;
        }
        tm0 = fmaxf(tm0, fmaxf(s[nt][0], s[nt][1]));
        tm1 = fmaxf(tm1, fmaxf(s[nt][2], s[nt][3]));
    }
    tm0 = fmaxf(tm0, __shfl_xor_sync(0xffffffffu, tm0, 1));
    tm0 = fmaxf(tm0, __shfl_xor_sync(0xffffffffu, tm0, 2));
    tm1 = fmaxf(tm1, __shfl_xor_sync(0xffffffffu, tm1, 1));
    tm1 = fmaxf(tm1, __shfl_xor_sync(0xffffffffu, tm1, 2));

    float mn0 = fmaxf(m0v, tm0), mn1 = fmaxf(m1v, tm1);
    float sc0 = __expf(m0v - mn0), sc1 = __expf(m1v - mn1);
    m0v = mn0; m1v = mn1;

    float ts0 = 0.f, ts1 = 0.f;
#pragma unroll
    for (int nt = 0; nt < 8; nt++) {
        float p0 = __expf(s[nt][0] - mn0);
        float p1 = __expf(s[nt][1] - mn0);
        float p2 = __expf(s[nt][2] - mn1);
        float p3 = __expf(s[nt][3] - mn1);
        ts0 += p0 + p1; ts1 += p2 + p3;
        __nv_bfloat16 h0, h1, h2, h3, l0, l1, l2, l3;
        split1(p0, h0, l0); split1(p1, h1, l1);
        split1(p2, h2, l2); split1(p3, h3, l3);
        int kp = nt >> 1, e = (nt & 1) * 2;
        pah[kp][e] = pkbf(h0, h1); pah[kp][e + 1] = pkbf(h2, h3);
        pal[kp][e] = pkbf(l0, l1); pal[kp][e + 1] = pkbf(l2, l3);
    }
    ts0 += __shfl_xor_sync(0xffffffffu, ts0, 1);
    ts0 += __shfl_xor_sync(0xffffffffu, ts0, 2);
    ts1 += __shfl_xor_sync(0xffffffffu, ts1, 1);
    ts1 += __shfl_xor_sync(0xffffffffu, ts1, 2);
    lsum0 = lsum0 * sc0 + ts0;
    lsum1 = lsum1 * sc1 + ts1;
#pragma unroll
    for (int nt = 0; nt < 8; nt++) {
        o[nt][0] *= sc0; o[nt][1] *= sc0;
        o[nt][2] *= sc1; o[nt][3] *= sc1;
    }
}

__device__ __forceinline__ void pv_tile(
    uint32_t st, int vrow, uint32_t vcb,
    const uint32_t (&pah)[4][4], const uint32_t (&pal)[4][4], float (&o)[8][4])
{
#pragma unroll
    for (int kp = 0; kp < 4; kp++) {
#pragma unroll
        for (int np = 0; np < 4; np++) {
            uint32_t off = SWZ128((uint32_t)((kp * 16 + vrow) * 128) + np * 32 + vcb);
            uint32_t vh_[4], vl_[4];
            ldsm_x4_t(vh_, st + 16384 + off);   // Vhi
            ldsm_x4_t(vl_, st + 24576 + off);   // Vlo
            mma_bf16(o[2 * np],     pah[kp], vh_);
            mma_bf16(o[2 * np],     pah[kp], vl_);
            mma_bf16(o[2 * np],     pal[kp], vh_);
            mma_bf16(o[2 * np + 1], pah[kp], vh_ + 2);
            mma_bf16(o[2 * np + 1], pah[kp], vl_ + 2);
            mma_bf16(o[2 * np + 1], pal[kp], vh_ + 2);
        }
    }
}

__global__ __launch_bounds__(256, 1) void attn_mma(
    __nv_bfloat16* __restrict__ ohi, __nv_bfloat16* __restrict__ olo)
{
    extern __shared__ char smc[];
    uint32_t sraw = smem_u32(smc);
    uint32_t sb = (sraw + 1023u) & ~1023u;
    char* smb = smc + (sb - sraw);

    const int tid = threadIdx.x, lid = tid & 31, wq = tid >> 5;
    const int qi = blockIdx.x, bh = blockIdx.y;
    const int b = bh >> 4, h = bh & 15;
    const int q0 = qi * 128;
    const size_t base2 = ((size_t)b * Ss * Dd + (size_t)h * DH) * 2;   // bytes
    const uint32_t qz = sb + A_QZ;

    // Q load (group 0)
#pragma unroll
    for (int i = 0; i < 8; i++) {
        int idx = tid + i * 256;
        int arr = idx >> 10, c = idx & 1023;
        int row = c >> 3; uint32_t colb = (uint32_t)((c & 7) * 16);
        const char* src = (const char*)(arr ? g_qlo : g_qhi) + base2 + (size_t)(q0 + row) * 2048 + colb;
        cp16(qz + arr * 16384 + SWZ128((uint32_t)(row * 128) + colb), src);
    }
    CP_COMMIT();

    const char* kvb[4] = {(const char*)g_khi, (const char*)g_klo,
                          (const char*)g_vhi, (const char*)g_vlo};
    auto kvload = [&](int kt) {
        uint32_t st = sb + (kt % 3) * AT_STG;
        int kv0 = kt * 64;
#pragma unroll
        for (int i = 0; i < 8; i++) {
            int idx = tid + i * 256;
            int arr = idx >> 9, c = idx & 511;
            int row = c >> 3; uint32_t colb = (uint32_t)((c & 7) * 16);
            cp16(st + arr * 8192 + SWZ128((uint32_t)(row * 128) + colb),
                 kvb[arr] + base2 + (size_t)(kv0 + row) * 2048 + colb);
        }
    };

    const int nkt = 2 * qi + 2;      // >= 2 always
    kvload(0); CP_COMMIT();
    kvload(1); CP_COMMIT();
    CP_WAIT(1);          // Q + tile0 done
    __syncthreads();

    // lane address components
    const int a_row = wq * 16 + (lid & 15);
    const uint32_t a_cb = (uint32_t)(((lid >> 4) & 1) * 16);
    const int mg = lid >> 3;
    const int krow = (mg >> 1) * 8 + (lid & 7);
    const uint32_t kcb = (uint32_t)((mg & 1) * 16);
    const int vrow = lid & 15;
    const uint32_t vcb = (uint32_t)((lid >> 4) * 16);

    // Q hi fragments -> registers (lo stays in smem)
    uint32_t qh[4][4];
#pragma unroll
    for (int kd = 0; kd < 4; kd++)
        ldsm_x4(qh[kd], qz + SWZ128((uint32_t)(a_row * 128) + kd * 32 + a_cb));

    float o[8][4];
#pragma unroll
    for (int nt = 0; nt < 8; nt++)
#pragma unroll
        for (int e = 0; e < 4; e++) o[nt][e] = 0.f;
    float m0v = -INFINITY, m1v = -INFINITY, lsum0 = 0.f, lsum1 = 0.f;

    const int r0g = q0 + wq * 16 + (lid >> 2);
    const int r1g = r0g + 8;
    const int ktfull = 2 * qi;       // tiles [0, ktfull) need no mask

    // prologue: S for tile 0
    float s_cur[8][4];
    qk_tile(sb + 0 * AT_STG, qz, a_row, a_cb, krow, kcb, qh, s_cur);

    for (int kt = 0; kt < nkt; kt++) {
        const bool havenext = (kt + 1 < nkt);
        if (kt + 2 < nkt) { kvload(kt + 2); CP_COMMIT(); }
        if (havenext) {
            if (kt + 2 < nkt) { CP_WAIT(1); } else { CP_WAIT(0); }
            __syncthreads();   // stage (kt+1) ready for all warps
        }

        // issue next tile's QK MMAs first: overlaps with softmax ALU below
        float s_next[8][4];
        if (havenext)
            qk_tile(sb + ((kt + 1) % 3) * AT_STG, qz, a_row, a_cb, krow, kcb, qh, s_next);

        uint32_t pah[4][4], pal[4][4];
        if (kt < ktfull)
            softmax_tile<false>(s_cur, kt * 64, r0g, r1g, lid, pah, pal,
                                o, m0v, m1v, lsum0, lsum1);
        else
            softmax_tile<true>(s_cur, kt * 64, r0g, r1g, lid, pah, pal,
                               o, m0v, m1v, lsum0, lsum1);

        pv_tile(sb + (kt % 3) * AT_STG, vrow, vcb, pah, pal, o);

        if (havenext) {
#pragma unroll
            for (int nt = 0; nt < 8; nt++)
#pragma unroll
                for (int e = 0; e < 4; e++) s_cur[nt][e] = s_next[nt][e];
        }
        __syncthreads();   // all warps done reading stage kt before it's rewritten
    }

    // epilogue: normalize, hi/lo split, stage in smem, coalesced store
    float il0 = 1.f / lsum0, il1 = 1.f / lsum1;
    {
        int rs0 = wq * 16 + (lid >> 2);
#pragma unroll
        for (int nt = 0; nt < 8; nt++) {
            uint32_t colb = (uint32_t)(nt * 16 + (lid & 3) * 4);
            float v0 = o[nt][0] * il0, v1 = o[nt][1] * il0;
            float v2 = o[nt][2] * il1, v3 = o[nt][3] * il1;
            __nv_bfloat16 h0, h1, h2, h3, l0, l1, l2, l3;
            split1(v0, h0, l0); split1(v1, h1, l1);
            split1(v2, h2, l2); split1(v3, h3, l3);
            *(uint32_t*)(smb + A_QZ + rs0 * 128 + colb) = pkbf(h0, h1);
            *(uint32_t*)(smb + A_QZ + (rs0 + 8) * 128 + colb) = pkbf(h2, h3);
            *(uint32_t*)(smb + A_QZ + 16384 + rs0 * 128 + colb) = pkbf(l0, l1);
            *(uint32_t*)(smb + A_QZ + 16384 + (rs0 + 8) * 128 + colb) = pkbf(l2, l3);
        }
    }
    __syncthreads();
#pragma unroll
    for (int i = 0; i < 8; i++) {
        int idx = tid + i * 256;
        int arr = idx >> 10, c = idx & 1023;
        int row = c >> 3; uint32_t colb = (uint32_t)((c & 7) * 16);
        uint4 v = *(uint4*)(smb + A_QZ + arr * 16384 + row * 128 + colb);
        char* dst = (char*)(arr ? olo : ohi) + base2 + (size_t)(q0 + row) * 2048 + colb;
        *(uint4*)dst = v;
    }
}

// ---------------- launch ----------------
extern "C" void kernel_launch(void* const* d_in, const int* in_sizes, int n_in,
                              void* d_out, int out_size)
{
    const float* x  = (const float*)d_in[0];
    const float* Wq = (const float*)d_in[1];
    const float* bq = (const float*)d_in[2];
    const float* Wk = (const float*)d_in[3];
    const float* bk = (const float*)d_in[4];
    const float* Wv = (const float*)d_in[5];
    const float* bv = (const float*)d_in[6];
    const float* Wo = (const float*)d_in[7];
    const float* bo = (const float*)d_in[8];
    float* out = (float*)d_out;

    __nv_bfloat16 *xhi, *xlo, *ahi, *alo, *wthi, *wtlo;
    cudaGetSymbolAddress((void**)&xhi,  g_xhi);
    cudaGetSymbolAddress((void**)&xlo,  g_xlo);
    cudaGetSymbolAddress((void**)&ahi,  g_ahi);
    cudaGetSymbolAddress((void**)&alo,  g_alo);
    cudaGetSymbolAddress((void**)&wthi, g_wthi);
    cudaGetSymbolAddress((void**)&wtlo, g_wtlo);

    cudaFuncSetAttribute(gemm_mma<0>,
                         cudaFuncAttributeMaxDynamicSharedMemorySize, GEMM_SMEM);
    cudaFuncSetAttribute(gemm_mma<1>,
                         cudaFuncAttributeMaxDynamicSharedMemorySize, GEMM_SMEM);
    cudaFuncSetAttribute(attn_mma,
                         cudaFuncAttributeMaxDynamicSharedMemorySize, ATT_SMEM);

    transpose_split<<<dim3(32, 32, 4), dim3(32, 8)>>>(Wq, Wk, Wv, Wo, wthi, wtlo);
    split_f32<<<(MM * Dd) / 1024, 256>>>(x, xhi, xlo);

    // Fused QKV projection: one launch, outputs routed to separate q/k/v buffers
    gemm_mma<0><<<dim3(24, MM / BM), 256, GEMM_SMEM>>>(bq, bk, bv, nullptr);

    attn_mma<<<dim3(Ss / 128, Bb * Hh), 256, ATT_SMEM>>>(ahi, alo);

    // Output projection
    gemm_mma<1><<<dim3(8, MM / BM), 256, GEMM_SMEM>>>(bo, nullptr, nullptr, out);
}

// round 9
// speedup vs baseline: 1.0438x; 1.0438x over previous
#include <cuda_runtime.h>
#include <cuda_bf16.h>
#include <math.h>
#include <stdint.h>

// Problem constants
constexpr int Bb = 2, Ss = 2048, Dd = 1024, Hh = 16, DH = 64;
constexpr int MM = Bb * Ss;       // 4096 rows

// ---------------- scratch (no cudaMalloc allowed) ----------------
__device__ __nv_bfloat16 g_xhi[MM * Dd];
__device__ __nv_bfloat16 g_xlo[MM * Dd];
__device__ __nv_bfloat16 g_qhi[MM * Dd];
__device__ __nv_bfloat16 g_qlo[MM * Dd];
__device__ __nv_bfloat16 g_khi[MM * Dd];
__device__ __nv_bfloat16 g_klo[MM * Dd];
__device__ __nv_bfloat16 g_vhi[MM * Dd];
__device__ __nv_bfloat16 g_vlo[MM * Dd];
__device__ __nv_bfloat16 g_ahi[MM * Dd];
__device__ __nv_bfloat16 g_alo[MM * Dd];
__device__ __nv_bfloat16 g_wthi[4 * Dd * Dd];    // transposed weights [N,K], Wq|Wk|Wv|Wo
__device__ __nv_bfloat16 g_wtlo[4 * Dd * Dd];

// ================= helpers =================
__device__ __forceinline__ uint32_t smem_u32(const void* p) {
    uint32_t a;
    asm("{ .reg .u64 t; cvta.to.shared.u64 t, %1; cvt.u32.u64 %0, t; }" : "=r"(a) : "l"(p));
    return a;
}
__device__ __forceinline__ void ldsm_x4(uint32_t* r, uint32_t a) {
    asm volatile("ldmatrix.sync.aligned.m8n8.x4.shared.b16 {%0,%1,%2,%3}, [%4];"
                 : "=r"(r[0]), "=r"(r[1]), "=r"(r[2]), "=r"(r[3]) : "r"(a));
}
__device__ __forceinline__ void ldsm_x4_t(uint32_t* r, uint32_t a) {
    asm volatile("ldmatrix.sync.aligned.m8n8.x4.trans.shared.b16 {%0,%1,%2,%3}, [%4];"
                 : "=r"(r[0]), "=r"(r[1]), "=r"(r[2]), "=r"(r[3]) : "r"(a));
}
__device__ __forceinline__ void mma_bf16(float* c, const uint32_t* a, const uint32_t* b) {
    asm volatile("mma.sync.aligned.m16n8k16.row.col.f32.bf16.bf16.f32 "
                 "{%0,%1,%2,%3}, {%4,%5,%6,%7}, {%8,%9}, {%0,%1,%2,%3};"
                 : "+f"(c[0]), "+f"(c[1]), "+f"(c[2]), "+f"(c[3])
                 : "r"(a[0]), "r"(a[1]), "r"(a[2]), "r"(a[3]), "r"(b[0]), "r"(b[1]));
}
__device__ __forceinline__ void cp16(uint32_t dst, const void* src) {
    asm volatile("cp.async.cg.shared.global [%0], [%1], 16;" :: "r"(dst), "l"(src));
}
#define CP_COMMIT() asm volatile("cp.async.commit_group;" ::: "memory")
#define CP_WAIT(n)  asm volatile("cp.async.wait_group %0;" :: "n"(n) : "memory")
#define SWZ128(off) ((off) ^ (((off) >> 3) & 0x70))

__device__ __forceinline__ void split1(float x, __nv_bfloat16& h, __nv_bfloat16& l) {
    h = __float2bfloat16(x);
    l = __float2bfloat16(x - __bfloat162float(h));
}
__device__ __forceinline__ uint32_t pkbf(__nv_bfloat16 a, __nv_bfloat16 b) {
    uint16_t ua = *(uint16_t*)&a, ub = *(uint16_t*)&b;
    return (uint32_t)ua | ((uint32_t)ub << 16);
}

// ================= split kernels =================
__global__ __launch_bounds__(256) void split_f32(
    const float* __restrict__ in, __nv_bfloat16* __restrict__ hi,
    __nv_bfloat16* __restrict__ lo)
{
    int i = blockIdx.x * 256 + threadIdx.x;
    float4 v = ((const float4*)in)[i];
    __nv_bfloat16 h0, h1, h2, h3, l0, l1, l2, l3;
    split1(v.x, h0, l0); split1(v.y, h1, l1); split1(v.z, h2, l2); split1(v.w, h3, l3);
    uint2 hp, lp;
    hp.x = pkbf(h0, h1); hp.y = pkbf(h2, h3);
    lp.x = pkbf(l0, l1); lp.y = pkbf(l2, l3);
    ((uint2*)hi)[i] = hp;
    ((uint2*)lo)[i] = lp;
}

// transpose W [K,N] -> Wt [N,K] bf16 hi/lo, for 4 weights (blockIdx.z)
__global__ __launch_bounds__(256) void transpose_split(
    const float* __restrict__ W0, const float* __restrict__ W1,
    const float* __restrict__ W2, const float* __restrict__ W3,
    __nv_bfloat16* __restrict__ hi, __nv_bfloat16* __restrict__ lo)
{
    __shared__ float sm[32][33];
    const float* W = (blockIdx.z == 0) ? W0 : (blockIdx.z == 1) ? W1 : (blockIdx.z == 2) ? W2 : W3;
    const int tx = threadIdx.x, ty = threadIdx.y;
    const int k0 = blockIdx.y * 32, n0 = blockIdx.x * 32;
#pragma unroll
    for (int i = 0; i < 4; i++)
        sm[ty + 8 * i][tx] = W[(size_t)(k0 + ty + 8 * i) * Dd + n0 + tx];
    __syncthreads();
    size_t zb = (size_t)blockIdx.z * Dd * Dd;
#pragma unroll
    for (int i = 0; i < 4; i++) {
        float v = sm[tx][ty + 8 * i];
        __nv_bfloat16 h, l; split1(v, h, l);
        size_t o = zb + (size_t)(n0 + ty + 8 * i) * Dd + k0 + tx;
        hi[o] = h; lo[o] = l;
    }
}

// ================= mma.sync GEMM (256 threads, known-good config) =================
constexpr int BM = 128, BN = 128, BKC = 64;
constexpr int STG_BYTES = 65536;
constexpr int OFF_AHI = 0, OFF_ALO = 16384, OFF_BHI = 32768, OFF_BLO = 49152;
constexpr int GEMM_SMEM = 2 * STG_BYTES + 1024;

template<int MODE>
__global__ __launch_bounds__(256, 1) void gemm_mma(
    const float* __restrict__ bias0, const float* __restrict__ bias1,
    const float* __restrict__ bias2, float* __restrict__ C)
{
    extern __shared__ char smc[];
    uint32_t sraw = smem_u32(smc);
    uint32_t sb = (sraw + 1023u) & ~1023u;

    const int tid = threadIdx.x, lid = tid & 31, wid = tid >> 5;
    const int wm = wid >> 2, wn = wid & 3;
    const int m0 = blockIdx.y * BM;
    const int z = (MODE == 0) ? (blockIdx.x >> 3) : 3;
    const int n0 = (MODE == 0) ? ((blockIdx.x & 7) * BN) : (blockIdx.x * BN);

    const __nv_bfloat16* Ahi = (MODE == 0) ? g_xhi : g_ahi;
    const __nv_bfloat16* Alo = (MODE == 0) ? g_xlo : g_alo;
    const __nv_bfloat16* Bhi = g_wthi + (size_t)z * Dd * Dd;
    const __nv_bfloat16* Blo = g_wtlo + (size_t)z * Dd * Dd;
    const float* bias = (MODE == 1) ? bias0 : ((z == 0) ? bias0 : (z == 1) ? bias1 : bias2);
    __nv_bfloat16* Chi = nullptr;
    __nv_bfloat16* Clo = nullptr;
    if (MODE == 0) {
        Chi = (z == 0) ? g_qhi : (z == 1) ? g_khi : g_vhi;
        Clo = (z == 0) ? g_qlo : (z == 1) ? g_klo : g_vlo;
    }

    uint32_t dsto[4];
    int rowA[4], rowB[4];
    uint32_t coff[4];
#pragma unroll
    for (int i = 0; i < 4; i++) {
        int idx = tid + i * 256;
        int r = idx >> 3;
        uint32_t off = (uint32_t)(r * 128 + (idx & 7) * 16);
        dsto[i] = SWZ128(off);
        rowA[i] = m0 + r;
        rowB[i] = n0 + r;
        coff[i] = (uint32_t)((idx & 7) * 16);
    }

    auto prefetch = [&](int chunk, int s) {
        uint32_t st = sb + s * STG_BYTES;
        size_t kb = (size_t)chunk * BKC * 2;
#pragma unroll
        for (int i = 0; i < 4; i++) {
            size_t ga = (size_t)rowA[i] * (Dd * 2) + kb + coff[i];
            size_t gb = (size_t)rowB[i] * (Dd * 2) + kb + coff[i];
            cp16(st + OFF_AHI + dsto[i], (const char*)Ahi + ga);
            cp16(st + OFF_ALO + dsto[i], (const char*)Alo + ga);
            cp16(st + OFF_BHI + dsto[i], (const char*)Bhi + gb);
            cp16(st + OFF_BLO + dsto[i], (const char*)Blo + gb);
        }
    };

    float acc[4][4][4];
#pragma unroll
    for (int mt = 0; mt < 4; mt++)
#pragma unroll
        for (int nt = 0; nt < 4; nt++)
#pragma unroll
            for (int e = 0; e < 4; e++) acc[mt][nt][e] = 0.f;

    prefetch(0, 0);
    CP_COMMIT();

    const int a_row = wm * 64 + (lid & 15);
    const uint32_t a_cb = (uint32_t)(((lid >> 4) & 1) * 16);
    const int mg = lid >> 3;
    const int b_row0 = wn * 32 + (mg >> 1) * 8 + (lid & 7);
    const uint32_t b_cb = (uint32_t)((mg & 1) * 16);

    const int NIT = Dd / BKC;   // 16
    for (int it = 0; it < NIT; it++) {
        const int s = it & 1;
        if (it + 1 < NIT) {
            prefetch(it + 1, (it + 1) & 1);
            CP_COMMIT();
            CP_WAIT(1);
        } else {
            CP_WAIT(0);
        }
        __syncthreads();

        uint32_t st = sb + s * STG_BYTES;
#pragma unroll
        for (int kt = 0; kt < 4; kt++) {
            uint32_t ah[4][4], al[4][4];
#pragma unroll
            for (int mt = 0; mt < 4; mt++) {
                uint32_t off = (uint32_t)((a_row + mt * 16) * 128) + kt * 32 + a_cb;
                off = SWZ128(off);
                ldsm_x4(ah[mt], st + OFF_AHI + off);
                ldsm_x4(al[mt], st + OFF_ALO + off);
            }
            uint32_t bh[4][2], bl[4][2];
#pragma unroll
            for (int p = 0; p < 2; p++) {
                uint32_t off = (uint32_t)((b_row0 + p * 16) * 128) + kt * 32 + b_cb;
                off = SWZ128(off);
                uint32_t r[4];
                ldsm_x4(r, st + OFF_BHI + off);
                bh[2 * p][0] = r[0]; bh[2 * p][1] = r[1];
                bh[2 * p + 1][0] = r[2]; bh[2 * p + 1][1] = r[3];
                ldsm_x4(r, st + OFF_BLO + off);
                bl[2 * p][0] = r[0]; bl[2 * p][1] = r[1];
                bl[2 * p + 1][0] = r[2]; bl[2 * p + 1][1] = r[3];
            }
#pragma unroll
            for (int mt = 0; mt < 4; mt++)
#pragma unroll
                for (int nt = 0; nt < 4; nt++) {
                    mma_bf16(acc[mt][nt], ah[mt], bh[nt]);
                    mma_bf16(acc[mt][nt], ah[mt], bl[nt]);
                    mma_bf16(acc[mt][nt], al[mt], bh[nt]);
                }
        }
        __syncthreads();
    }

    // epilogue
#pragma unroll
    for (int nt = 0; nt < 4; nt++) {
        int c0 = n0 + wn * 32 + nt * 8 + (lid & 3) * 2;
        float b0 = bias[c0], b1 = bias[c0 + 1];
#pragma unroll
        for (int mt = 0; mt < 4; mt++) {
            int r0 = m0 + wm * 64 + mt * 16 + (lid >> 2);
            float v0 = acc[mt][nt][0] + b0, v1 = acc[mt][nt][1] + b1;
            float v2 = acc[mt][nt][2] + b0, v3 = acc[mt][nt][3] + b1;
            if (MODE == 0) {
                __nv_bfloat16 h0, h1, h2, h3, l0, l1, l2, l3;
                split1(v0, h0, l0); split1(v1, h1, l1);
                split1(v2, h2, l2); split1(v3, h3, l3);
                *(uint32_t*)&Chi[(size_t)r0 * Dd + c0] = pkbf(h0, h1);
                *(uint32_t*)&Clo[(size_t)r0 * Dd + c0] = pkbf(l0, l1);
                *(uint32_t*)&Chi[(size_t)(r0 + 8) * Dd + c0] = pkbf(h2, h3);
                *(uint32_t*)&Clo[(size_t)(r0 + 8) * Dd + c0] = pkbf(l2, l3);
            } else {
                float2 w0 = {v0, v1}, w1 = {v2, v3};
                *(float2*)&C[(size_t)r0 * Dd + c0] = w0;
                *(float2*)&C[(size_t)(r0 + 8) * Dd + c0] = w1;
            }
        }
    }
}

// ================= Flash attention with mma.sync (causal) =================
// R7 structure (3-stage KV pipeline, mask-free fast path) + heavy-first CTA
// ordering + exp2-domain softmax.
constexpr int AT_STG = 32768;                      // Khi|Klo|Vhi|Vlo 8KB each
constexpr int A_QZ = 3 * AT_STG;                   // Q hi 16K + lo 16K (reused for out staging)
constexpr int ATT_SMEM = A_QZ + 32768 + 1024;
constexpr float SCL2 = 0.03125f * 1.4426950408889634f;   // (1/32) * log2(e)

template<bool MASK>
__device__ __forceinline__ void attn_tile(
    uint32_t st, int kv0, int r0g, int r1g, int lid,
    int krow, uint32_t kcb, int vrow, uint32_t vcb,
    const uint32_t (&qh)[4][4], const uint32_t (&ql)[4][4],
    float (&o)[8][4], float& m0v, float& m1v, float& lsum0, float& lsum1)
{
    // S = Q K^T (3-term)
    float s[8][4];
#pragma unroll
    for (int nt = 0; nt < 8; nt++)
#pragma unroll
        for (int e = 0; e < 4; e++) s[nt][e] = 0.f;
#pragma unroll
    for (int kd = 0; kd < 4; kd++) {
#pragma unroll
        for (int np = 0; np < 4; np++) {
            uint32_t off = SWZ128((uint32_t)((np * 16 + krow) * 128) + kd * 32 + kcb);
            uint32_t bh_[4], bl_[4];
            ldsm_x4(bh_, st + 0 + off);        // Khi
            ldsm_x4(bl_, st + 8192 + off);     // Klo
            mma_bf16(s[2 * np],     qh[kd], bh_);
            mma_bf16(s[2 * np],     qh[kd], bl_);
            mma_bf16(s[2 * np],     ql[kd], bh_);
            mma_bf16(s[2 * np + 1], qh[kd], bh_ + 2);
            mma_bf16(s[2 * np + 1], qh[kd], bl_ + 2);
            mma_bf16(s[2 * np + 1], ql[kd], bh_ + 2);
        }
    }

    // scale into log2 domain (+ causal mask if MASK) + row max
    float tm0 = -INFINITY, tm1 = -INFINITY;
#pragma unroll
    for (int nt = 0; nt < 8; nt++) {
        if (MASK) {
            int kg = kv0 + nt * 8 + (lid & 3) * 2;
            s[nt][0] = (kg     <= r0g) ? s[nt][0] * SCL2 : -INFINITY;
            s[nt][1] = (kg + 1 <= r0g) ? s[nt][1] * SCL2 : -INFINITY;
            s[nt][2] = (kg     <= r1g) ? s[nt][2] * SCL2 : -INFINITY;
            s[nt][3] = (kg + 1 <= r1g) ? s[nt][3] * SCL2 : -INFINITY;
        } else {
            s[nt][0] *= SCL2; s[nt][1] *= SCL2;
            s[nt][2] *= SCL2; s[nt][3] *= SCL2;
        }
        tm0 = fmaxf(tm0, fmaxf(s[nt][0], s[nt][1]));
        tm1 = fmaxf(tm1, fmaxf(s[nt][2], s[nt][3]));
    }
    tm0 = fmaxf(tm0, __shfl_xor_sync(0xffffffffu, tm0, 1));
    tm0 = fmaxf(tm0, __shfl_xor_sync(0xffffffffu, tm0, 2));
    tm1 = fmaxf(tm1, __shfl_xor_sync(0xffffffffu, tm1, 1));
    tm1 = fmaxf(tm1, __shfl_xor_sync(0xffffffffu, tm1, 2));

    float mn0 = fmaxf(m0v, tm0), mn1 = fmaxf(m1v, tm1);
    float sc0 = exp2f(m0v - mn0), sc1 = exp2f(m1v - mn1);
    m0v = mn0; m1v = mn1;

    // P = 2^(S - m), build bf16 hi/lo A-fragments
    uint32_t pah[4][4], pal[4][4];
    float ts0 = 0.f, ts1 = 0.f;
#pragma unroll
    for (int nt = 0; nt < 8; nt++) {
        float p0 = exp2f(s[nt][0] - mn0);
        float p1 = exp2f(s[nt][1] - mn0);
        float p2 = exp2f(s[nt][2] - mn1);
        float p3 = exp2f(s[nt][3] - mn1);
        ts0 += p0 + p1; ts1 += p2 + p3;
        __nv_bfloat16 h0, h1, h2, h3, l0, l1, l2, l3;
        split1(p0, h0, l0); split1(p1, h1, l1);
        split1(p2, h2, l2); split1(p3, h3, l3);
        int kp = nt >> 1, e = (nt & 1) * 2;
        pah[kp][e] = pkbf(h0, h1); pah[kp][e + 1] = pkbf(h2, h3);
        pal[kp][e] = pkbf(l0, l1); pal[kp][e + 1] = pkbf(l2, l3);
    }
    ts0 += __shfl_xor_sync(0xffffffffu, ts0, 1);
    ts0 += __shfl_xor_sync(0xffffffffu, ts0, 2);
    ts1 += __shfl_xor_sync(0xffffffffu, ts1, 1);
    ts1 += __shfl_xor_sync(0xffffffffu, ts1, 2);
    lsum0 = lsum0 * sc0 + ts0;
    lsum1 = lsum1 * sc1 + ts1;
#pragma unroll
    for (int nt = 0; nt < 8; nt++) {
        o[nt][0] *= sc0; o[nt][1] *= sc0;
        o[nt][2] *= sc1; o[nt][3] *= sc1;
    }

    // O += P V (3-term); V fragments via ldmatrix.trans
#pragma unroll
    for (int kp = 0; kp < 4; kp++) {
#pragma unroll
        for (int np = 0; np < 4; np++) {
            uint32_t off = SWZ128((uint32_t)((kp * 16 + vrow) * 128) + np * 32 + vcb);
            uint32_t vh_[4], vl_[4];
            ldsm_x4_t(vh_, st + 16384 + off);   // Vhi
            ldsm_x4_t(vl_, st + 24576 + off);   // Vlo
            mma_bf16(o[2 * np],     pah[kp], vh_);
            mma_bf16(o[2 * np],     pah[kp], vl_);
            mma_bf16(o[2 * np],     pal[kp], vh_);
            mma_bf16(o[2 * np + 1], pah[kp], vh_ + 2);
            mma_bf16(o[2 * np + 1], pah[kp], vl_ + 2);
            mma_bf16(o[2 * np + 1], pal[kp], vh_ + 2);
        }
    }
}

__global__ __launch_bounds__(256, 1) void attn_mma(
    __nv_bfloat16* __restrict__ ohi, __nv_bfloat16* __restrict__ olo)
{
    extern __shared__ char smc[];
    uint32_t sraw = smem_u32(smc);
    uint32_t sb = (sraw + 1023u) & ~1023u;
    char* smb = smc + (sb - sraw);

    const int tid = threadIdx.x, lid = tid & 31, wq = tid >> 5;
    // heavy-first: blockIdx.x = 0 gets the longest (most KV tiles) query block
    const int qi = (gridDim.x - 1) - blockIdx.x;
    const int bh = blockIdx.y;
    const int b = bh >> 4, h = bh & 15;
    const int q0 = qi * 128;
    const size_t base2 = ((size_t)b * Ss * Dd + (size_t)h * DH) * 2;   // bytes

    // Q load (group 0)
#pragma unroll
    for (int i = 0; i < 8; i++) {
        int idx = tid + i * 256;
        int arr = idx >> 10, c = idx & 1023;
        int row = c >> 3; uint32_t colb = (uint32_t)((c & 7) * 16);
        const char* src = (const char*)(arr ? g_qlo : g_qhi) + base2 + (size_t)(q0 + row) * 2048 + colb;
        cp16(sb + A_QZ + arr * 16384 + SWZ128((uint32_t)(row * 128) + colb), src);
    }
    CP_COMMIT();

    const char* kvb[4] = {(const char*)g_khi, (const char*)g_klo,
                          (const char*)g_vhi, (const char*)g_vlo};
    auto kvload = [&](int kt) {
        uint32_t st = sb + (kt % 3) * AT_STG;
        int kv0 = kt * 64;
#pragma unroll
        for (int i = 0; i < 8; i++) {
            int idx = tid + i * 256;
            int arr = idx >> 9, c = idx & 511;
            int row = c >> 3; uint32_t colb = (uint32_t)((c & 7) * 16);
            cp16(st + arr * 8192 + SWZ128((uint32_t)(row * 128) + colb),
                 kvb[arr] + base2 + (size_t)(kv0 + row) * 2048 + colb);
        }
    };

    const int nkt = 2 * qi + 2;
    kvload(0); CP_COMMIT();
    if (nkt > 1) { kvload(1); CP_COMMIT(); }
    CP_WAIT(2);          // Q group done
    __syncthreads();

    // Q fragments -> registers (4 dim-chunks of 16)
    uint32_t qh[4][4], ql[4][4];
    {
        const int a_row = wq * 16 + (lid & 15);
        const uint32_t a_cb = (uint32_t)(((lid >> 4) & 1) * 16);
#pragma unroll
        for (int kd = 0; kd < 4; kd++) {
            uint32_t off = SWZ128((uint32_t)(a_row * 128) + kd * 32 + a_cb);
            ldsm_x4(qh[kd], sb + A_QZ + off);
            ldsm_x4(ql[kd], sb + A_QZ + 16384 + off);
        }
    }

    float o[8][4];
#pragma unroll
    for (int nt = 0; nt < 8; nt++)
#pragma unroll
        for (int e = 0; e < 4; e++) o[nt][e] = 0.f;
    float m0v = -INFINITY, m1v = -INFINITY, lsum0 = 0.f, lsum1 = 0.f;

    const int r0g = q0 + wq * 16 + (lid >> 2);
    const int r1g = r0g + 8;
    const int mg = lid >> 3;
    const int krow = (mg >> 1) * 8 + (lid & 7);
    const uint32_t kcb = (uint32_t)((mg & 1) * 16);
    const int vrow = lid & 15;
    const uint32_t vcb = (uint32_t)((lid >> 4) * 16);

    const int ktfull = 2 * qi;     // tiles [0, ktfull) need no mask
    for (int kt = 0; kt < nkt; kt++) {
        if (kt + 2 < nkt) { kvload(kt + 2); CP_COMMIT(); CP_WAIT(2); }
        else if (kt + 1 < nkt) { CP_WAIT(1); }
        else { CP_WAIT(0); }
        __syncthreads();
        uint32_t st = sb + (kt % 3) * AT_STG;
        if (kt < ktfull)
            attn_tile<false>(st, kt * 64, r0g, r1g, lid, krow, kcb, vrow, vcb,
                             qh, ql, o, m0v, m1v, lsum0, lsum1);
        else
            attn_tile<true>(st, kt * 64, r0g, r1g, lid, krow, kcb, vrow, vcb,
                            qh, ql, o, m0v, m1v, lsum0, lsum1);
        __syncthreads();
    }

    // epilogue: normalize, hi/lo split, stage in smem, coalesced store
    float il0 = 1.f / lsum0, il1 = 1.f / lsum1;
    {
        int rs0 = wq * 16 + (lid >> 2);
#pragma unroll
        for (int nt = 0; nt < 8; nt++) {
            uint32_t colb = (uint32_t)(nt * 16 + (lid & 3) * 4);
            float v0 = o[nt][0] * il0, v1 = o[nt][1] * il0;
            float v2 = o[nt][2] * il1, v3 = o[nt][3] * il1;
            __nv_bfloat16 h0, h1, h2, h3, l0, l1, l2, l3;
            split1(v0, h0, l0); split1(v1, h1, l1);
            split1(v2, h2, l2); split1(v3, h3, l3);
            *(uint32_t*)(smb + A_QZ + rs0 * 128 + colb) = pkbf(h0, h1);
            *(uint32_t*)(smb + A_QZ + (rs0 + 8) * 128 + colb) = pkbf(h2, h3);
            *(uint32_t*)(smb + A_QZ + 16384 + rs0 * 128 + colb) = pkbf(l0, l1);
            *(uint32_t*)(smb + A_QZ + 16384 + (rs0 + 8) * 128 + colb) = pkbf(l2, l3);
        }
    }
    __syncthreads();
#pragma unroll
    for (int i = 0; i < 8; i++) {
        int idx = tid + i * 256;
        int arr = idx >> 10, c = idx & 1023;
        int row = c >> 3; uint32_t colb = (uint32_t)((c & 7) * 16);
        uint4 v = *(uint4*)(smb + A_QZ + arr * 16384 + row * 128 + colb);
        char* dst = (char*)(arr ? olo : ohi) + base2 + (size_t)(q0 + row) * 2048 + colb;
        *(uint4*)dst = v;
    }
}

// ---------------- launch ----------------
extern "C" void kernel_launch(void* const* d_in, const int* in_sizes, int n_in,
                              void* d_out, int out_size)
{
    const float* x  = (const float*)d_in[0];
    const float* Wq = (const float*)d_in[1];
    const float* bq = (const float*)d_in[2];
    const float* Wk = (const float*)d_in[3];
    const float* bk = (const float*)d_in[4];
    const float* Wv = (const float*)d_in[5];
    const float* bv = (const float*)d_in[6];
    const float* Wo = (const float*)d_in[7];
    const float* bo = (const float*)d_in[8];
    float* out = (float*)d_out;

    __nv_bfloat16 *xhi, *xlo, *ahi, *alo, *wthi, *wtlo;
    cudaGetSymbolAddress((void**)&xhi,  g_xhi);
    cudaGetSymbolAddress((void**)&xlo,  g_xlo);
    cudaGetSymbolAddress((void**)&ahi,  g_ahi);
    cudaGetSymbolAddress((void**)&alo,  g_alo);
    cudaGetSymbolAddress((void**)&wthi, g_wthi);
    cudaGetSymbolAddress((void**)&wtlo, g_wtlo);

    cudaFuncSetAttribute(gemm_mma<0>,
                         cudaFuncAttributeMaxDynamicSharedMemorySize, GEMM_SMEM);
    cudaFuncSetAttribute(gemm_mma<1>,
                         cudaFuncAttributeMaxDynamicSharedMemorySize, GEMM_SMEM);
    cudaFuncSetAttribute(attn_mma,
                         cudaFuncAttributeMaxDynamicSharedMemorySize, ATT_SMEM);

    transpose_split<<<dim3(32, 32, 4), dim3(32, 8)>>>(Wq, Wk, Wv, Wo, wthi, wtlo);
    split_f32<<<(MM * Dd) / 1024, 256>>>(x, xhi, xlo);

    // Fused QKV projection: one launch, outputs routed to separate q/k/v buffers
    gemm_mma<0><<<dim3(24, MM / BM), 256, GEMM_SMEM>>>(bq, bk, bv, nullptr);

    attn_mma<<<dim3(Ss / 128, Bb * Hh), 256, ATT_SMEM>>>(ahi, alo);

    // Output projection
    gemm_mma<1><<<dim3(8, MM / BM), 256, GEMM_SMEM>>>(bo, nullptr, nullptr, out);
}

// round 10
// speedup vs baseline: 1.0802x; 1.0349x over previous
#include <cuda_runtime.h>
#include <cuda_bf16.h>
#include <math.h>
#include <stdint.h>

// Problem constants
constexpr int Bb = 2, Ss = 2048, Dd = 1024, Hh = 16, DH = 64;
constexpr int MM = Bb * Ss;       // 4096 rows

// ---------------- scratch (no cudaMalloc allowed) ----------------
__device__ __nv_bfloat16 g_xhi[MM * Dd];
__device__ __nv_bfloat16 g_xlo[MM * Dd];
__device__ __nv_bfloat16 g_qhi[MM * Dd];
__device__ __nv_bfloat16 g_qlo[MM * Dd];
__device__ __nv_bfloat16 g_khi[MM * Dd];
__device__ __nv_bfloat16 g_klo[MM * Dd];
__device__ __nv_bfloat16 g_vhi[MM * Dd];
__device__ __nv_bfloat16 g_vlo[MM * Dd];
__device__ __nv_bfloat16 g_ahi[MM * Dd];
__device__ __nv_bfloat16 g_alo[MM * Dd];
__device__ __nv_bfloat16 g_wthi[4 * Dd * Dd];    // transposed weights [N,K], Wq|Wk|Wv|Wo
__device__ __nv_bfloat16 g_wtlo[4 * Dd * Dd];

// ================= helpers =================
__device__ __forceinline__ uint32_t smem_u32(const void* p) {
    uint32_t a;
    asm("{ .reg .u64 t; cvta.to.shared.u64 t, %1; cvt.u32.u64 %0, t; }" : "=r"(a) : "l"(p));
    return a;
}
__device__ __forceinline__ void ldsm_x4(uint32_t* r, uint32_t a) {
    asm volatile("ldmatrix.sync.aligned.m8n8.x4.shared.b16 {%0,%1,%2,%3}, [%4];"
                 : "=r"(r[0]), "=r"(r[1]), "=r"(r[2]), "=r"(r[3]) : "r"(a));
}
__device__ __forceinline__ void ldsm_x4_t(uint32_t* r, uint32_t a) {
    asm volatile("ldmatrix.sync.aligned.m8n8.x4.trans.shared.b16 {%0,%1,%2,%3}, [%4];"
                 : "=r"(r[0]), "=r"(r[1]), "=r"(r[2]), "=r"(r[3]) : "r"(a));
}
__device__ __forceinline__ void mma_bf16(float* c, const uint32_t* a, const uint32_t* b) {
    asm volatile("mma.sync.aligned.m16n8k16.row.col.f32.bf16.bf16.f32 "
                 "{%0,%1,%2,%3}, {%4,%5,%6,%7}, {%8,%9}, {%0,%1,%2,%3};"
                 : "+f"(c[0]), "+f"(c[1]), "+f"(c[2]), "+f"(c[3])
                 : "r"(a[0]), "r"(a[1]), "r"(a[2]), "r"(a[3]), "r"(b[0]), "r"(b[1]));
}
__device__ __forceinline__ void cp16(uint32_t dst, const void* src) {
    asm volatile("cp.async.cg.shared.global [%0], [%1], 16;" :: "r"(dst), "l"(src));
}
#define CP_COMMIT() asm volatile("cp.async.commit_group;" ::: "memory")
#define CP_WAIT(n)  asm volatile("cp.async.wait_group %0;" :: "n"(n) : "memory")
#define SWZ128(off) ((off) ^ (((off) >> 3) & 0x70))

__device__ __forceinline__ void split1(float x, __nv_bfloat16& h, __nv_bfloat16& l) {
    h = __float2bfloat16(x);
    l = __float2bfloat16(x - __bfloat162float(h));
}
__device__ __forceinline__ uint32_t pkbf(__nv_bfloat16 a, __nv_bfloat16 b) {
    uint16_t ua = *(uint16_t*)&a, ub = *(uint16_t*)&b;
    return (uint32_t)ua | ((uint32_t)ub << 16);
}

// ================= split kernels =================
__global__ __launch_bounds__(256) void split_f32(
    const float* __restrict__ in, __nv_bfloat16* __restrict__ hi,
    __nv_bfloat16* __restrict__ lo)
{
    int i = blockIdx.x * 256 + threadIdx.x;
    float4 v = ((const float4*)in)[i];
    __nv_bfloat16 h0, h1, h2, h3, l0, l1, l2, l3;
    split1(v.x, h0, l0); split1(v.y, h1, l1); split1(v.z, h2, l2); split1(v.w, h3, l3);
    uint2 hp, lp;
    hp.x = pkbf(h0, h1); hp.y = pkbf(h2, h3);
    lp.x = pkbf(l0, l1); lp.y = pkbf(l2, l3);
    ((uint2*)hi)[i] = hp;
    ((uint2*)lo)[i] = lp;
}

// transpose W [K,N] -> Wt [N,K] bf16 hi/lo, for 4 weights (blockIdx.z)
__global__ __launch_bounds__(256) void transpose_split(
    const float* __restrict__ W0, const float* __restrict__ W1,
    const float* __restrict__ W2, const float* __restrict__ W3,
    __nv_bfloat16* __restrict__ hi, __nv_bfloat16* __restrict__ lo)
{
    __shared__ float sm[32][33];
    const float* W = (blockIdx.z == 0) ? W0 : (blockIdx.z == 1) ? W1 : (blockIdx.z == 2) ? W2 : W3;
    const int tx = threadIdx.x, ty = threadIdx.y;
    const int k0 = blockIdx.y * 32, n0 = blockIdx.x * 32;
#pragma unroll
    for (int i = 0; i < 4; i++)
        sm[ty + 8 * i][tx] = W[(size_t)(k0 + ty + 8 * i) * Dd + n0 + tx];
    __syncthreads();
    size_t zb = (size_t)blockIdx.z * Dd * Dd;
#pragma unroll
    for (int i = 0; i < 4; i++) {
        float v = sm[tx][ty + 8 * i];
        __nv_bfloat16 h, l; split1(v, h, l);
        size_t o = zb + (size_t)(n0 + ty + 8 * i) * Dd + k0 + tx;
        hi[o] = h; lo[o] = l;
    }
}

// ================= mma.sync GEMM (256 threads, known-good config) =================
constexpr int BM = 128, BN = 128, BKC = 64;
constexpr int STG_BYTES = 65536;
constexpr int OFF_AHI = 0, OFF_ALO = 16384, OFF_BHI = 32768, OFF_BLO = 49152;
constexpr int GEMM_SMEM = 2 * STG_BYTES + 1024;

template<int MODE>
__global__ __launch_bounds__(256, 1) void gemm_mma(
    const float* __restrict__ bias0, const float* __restrict__ bias1,
    const float* __restrict__ bias2, float* __restrict__ C)
{
    extern __shared__ char smc[];
    uint32_t sraw = smem_u32(smc);
    uint32_t sb = (sraw + 1023u) & ~1023u;

    const int tid = threadIdx.x, lid = tid & 31, wid = tid >> 5;
    const int wm = wid >> 2, wn = wid & 3;
    const int m0 = blockIdx.y * BM;
    const int z = (MODE == 0) ? (blockIdx.x >> 3) : 3;
    const int n0 = (MODE == 0) ? ((blockIdx.x & 7) * BN) : (blockIdx.x * BN);

    const __nv_bfloat16* Ahi = (MODE == 0) ? g_xhi : g_ahi;
    const __nv_bfloat16* Alo = (MODE == 0) ? g_xlo : g_alo;
    const __nv_bfloat16* Bhi = g_wthi + (size_t)z * Dd * Dd;
    const __nv_bfloat16* Blo = g_wtlo + (size_t)z * Dd * Dd;
    const float* bias = (MODE == 1) ? bias0 : ((z == 0) ? bias0 : (z == 1) ? bias1 : bias2);
    __nv_bfloat16* Chi = nullptr;
    __nv_bfloat16* Clo = nullptr;
    if (MODE == 0) {
        Chi = (z == 0) ? g_qhi : (z == 1) ? g_khi : g_vhi;
        Clo = (z == 0) ? g_qlo : (z == 1) ? g_klo : g_vlo;
    }

    uint32_t dsto[4];
    int rowA[4], rowB[4];
    uint32_t coff[4];
#pragma unroll
    for (int i = 0; i < 4; i++) {
        int idx = tid + i * 256;
        int r = idx >> 3;
        uint32_t off = (uint32_t)(r * 128 + (idx & 7) * 16);
        dsto[i] = SWZ128(off);
        rowA[i] = m0 + r;
        rowB[i] = n0 + r;
        coff[i] = (uint32_t)((idx & 7) * 16);
    }

    auto prefetch = [&](int chunk, int s) {
        uint32_t st = sb + s * STG_BYTES;
        size_t kb = (size_t)chunk * BKC * 2;
#pragma unroll
        for (int i = 0; i < 4; i++) {
            size_t ga = (size_t)rowA[i] * (Dd * 2) + kb + coff[i];
            size_t gb = (size_t)rowB[i] * (Dd * 2) + kb + coff[i];
            cp16(st + OFF_AHI + dsto[i], (const char*)Ahi + ga);
            cp16(st + OFF_ALO + dsto[i], (const char*)Alo + ga);
            cp16(st + OFF_BHI + dsto[i], (const char*)Bhi + gb);
            cp16(st + OFF_BLO + dsto[i], (const char*)Blo + gb);
        }
    };

    float acc[4][4][4];
#pragma unroll
    for (int mt = 0; mt < 4; mt++)
#pragma unroll
        for (int nt = 0; nt < 4; nt++)
#pragma unroll
            for (int e = 0; e < 4; e++) acc[mt][nt][e] = 0.f;

    prefetch(0, 0);
    CP_COMMIT();

    const int a_row = wm * 64 + (lid & 15);
    const uint32_t a_cb = (uint32_t)(((lid >> 4) & 1) * 16);
    const int mg = lid >> 3;
    const int b_row0 = wn * 32 + (mg >> 1) * 8 + (lid & 7);
    const uint32_t b_cb = (uint32_t)((mg & 1) * 16);

    const int NIT = Dd / BKC;   // 16
    for (int it = 0; it < NIT; it++) {
        const int s = it & 1;
        if (it + 1 < NIT) {
            prefetch(it + 1, (it + 1) & 1);
            CP_COMMIT();
            CP_WAIT(1);
        } else {
            CP_WAIT(0);
        }
        __syncthreads();

        uint32_t st = sb + s * STG_BYTES;
#pragma unroll
        for (int kt = 0; kt < 4; kt++) {
            uint32_t ah[4][4], al[4][4];
#pragma unroll
            for (int mt = 0; mt < 4; mt++) {
                uint32_t off = (uint32_t)((a_row + mt * 16) * 128) + kt * 32 + a_cb;
                off = SWZ128(off);
                ldsm_x4(ah[mt], st + OFF_AHI + off);
                ldsm_x4(al[mt], st + OFF_ALO + off);
            }
            uint32_t bh[4][2], bl[4][2];
#pragma unroll
            for (int p = 0; p < 2; p++) {
                uint32_t off = (uint32_t)((b_row0 + p * 16) * 128) + kt * 32 + b_cb;
                off = SWZ128(off);
                uint32_t r[4];
                ldsm_x4(r, st + OFF_BHI + off);
                bh[2 * p][0] = r[0]; bh[2 * p][1] = r[1];
                bh[2 * p + 1][0] = r[2]; bh[2 * p + 1][1] = r[3];
                ldsm_x4(r, st + OFF_BLO + off);
                bl[2 * p][0] = r[0]; bl[2 * p][1] = r[1];
                bl[2 * p + 1][0] = r[2]; bl[2 * p + 1][1] = r[3];
            }
#pragma unroll
            for (int mt = 0; mt < 4; mt++)
#pragma unroll
                for (int nt = 0; nt < 4; nt++) {
                    mma_bf16(acc[mt][nt], ah[mt], bh[nt]);
                    mma_bf16(acc[mt][nt], ah[mt], bl[nt]);
                    mma_bf16(acc[mt][nt], al[mt], bh[nt]);
                }
        }
        __syncthreads();
    }

    // epilogue
#pragma unroll
    for (int nt = 0; nt < 4; nt++) {
        int c0 = n0 + wn * 32 + nt * 8 + (lid & 3) * 2;
        float b0 = bias[c0], b1 = bias[c0 + 1];
#pragma unroll
        for (int mt = 0; mt < 4; mt++) {
            int r0 = m0 + wm * 64 + mt * 16 + (lid >> 2);
            float v0 = acc[mt][nt][0] + b0, v1 = acc[mt][nt][1] + b1;
            float v2 = acc[mt][nt][2] + b0, v3 = acc[mt][nt][3] + b1;
            if (MODE == 0) {
                __nv_bfloat16 h0, h1, h2, h3, l0, l1, l2, l3;
                split1(v0, h0, l0); split1(v1, h1, l1);
                split1(v2, h2, l2); split1(v3, h3, l3);
                *(uint32_t*)&Chi[(size_t)r0 * Dd + c0] = pkbf(h0, h1);
                *(uint32_t*)&Clo[(size_t)r0 * Dd + c0] = pkbf(l0, l1);
                *(uint32_t*)&Chi[(size_t)(r0 + 8) * Dd + c0] = pkbf(h2, h3);
                *(uint32_t*)&Clo[(size_t)(r0 + 8) * Dd + c0] = pkbf(l2, l3);
            } else {
                float2 w0 = {v0, v1}, w1 = {v2, v3};
                *(float2*)&C[(size_t)r0 * Dd + c0] = w0;
                *(float2*)&C[(size_t)(r0 + 8) * Dd + c0] = w1;
            }
        }
    }
}

// ================= Flash attention with mma.sync (causal) =================
// Max-free streaming softmax: softmax is shift-invariant and scores are bounded
// (|log2-domain| < ~60 << fp32 exp range), so no running max is needed.
// Each 64-key tile is processed in two 32-key halves: QK -> exp2/split -> PV,
// interleaving tensor and MUFU/ALU work and halving softmax register pressure.
// Per-thread partial lsum; lane reduction deferred to the epilogue.
constexpr int AT_STG = 32768;                      // Khi|Klo|Vhi|Vlo 8KB each
constexpr int A_QZ = 3 * AT_STG;                   // Q hi 16K + lo 16K (reused for out staging)
constexpr int ATT_SMEM = A_QZ + 32768 + 1024;
constexpr float SCL2 = 0.03125f * 1.4426950408889634f;   // (1/32) * log2(e)

template<bool MASK>
__device__ __forceinline__ void attn_tile(
    uint32_t st, int kv0, int r0g, int r1g, int lid,
    int krow, uint32_t kcb, int vrow, uint32_t vcb,
    const uint32_t (&qh)[4][4], const uint32_t (&ql)[4][4],
    float (&o)[8][4], float& lsum0, float& lsum1)
{
#pragma unroll
    for (int hf = 0; hf < 2; hf++) {
        // S = Q K^T over 32 keys (3-term)
        float s[4][4];
#pragma unroll
        for (int nt = 0; nt < 4; nt++)
#pragma unroll
            for (int e = 0; e < 4; e++) s[nt][e] = 0.f;
#pragma unroll
        for (int kd = 0; kd < 4; kd++) {
#pragma unroll
            for (int np = 0; np < 2; np++) {
                uint32_t off = SWZ128((uint32_t)((hf * 32 + np * 16 + krow) * 128) + kd * 32 + kcb);
                uint32_t bh_[4], bl_[4];
                ldsm_x4(bh_, st + 0 + off);        // Khi
                ldsm_x4(bl_, st + 8192 + off);     // Klo
                mma_bf16(s[2 * np],     qh[kd], bh_);
                mma_bf16(s[2 * np],     qh[kd], bl_);
                mma_bf16(s[2 * np],     ql[kd], bh_);
                mma_bf16(s[2 * np + 1], qh[kd], bh_ + 2);
                mma_bf16(s[2 * np + 1], qh[kd], bl_ + 2);
                mma_bf16(s[2 * np + 1], ql[kd], bh_ + 2);
            }
        }

        // P = 2^(scale*S) (no max shift), split to bf16 hi/lo A-fragments
        uint32_t pah[2][4], pal[2][4];
#pragma unroll
        for (int nt = 0; nt < 4; nt++) {
            float v0, v1, v2, v3;
            if (MASK) {
                int kg = kv0 + hf * 32 + nt * 8 + (lid & 3) * 2;
                v0 = (kg     <= r0g) ? s[nt][0] * SCL2 : -INFINITY;
                v1 = (kg + 1 <= r0g) ? s[nt][1] * SCL2 : -INFINITY;
                v2 = (kg     <= r1g) ? s[nt][2] * SCL2 : -INFINITY;
                v3 = (kg + 1 <= r1g) ? s[nt][3] * SCL2 : -INFINITY;
            } else {
                v0 = s[nt][0] * SCL2; v1 = s[nt][1] * SCL2;
                v2 = s[nt][2] * SCL2; v3 = s[nt][3] * SCL2;
            }
            float p0 = exp2f(v0), p1 = exp2f(v1);
            float p2 = exp2f(v2), p3 = exp2f(v3);
            lsum0 += p0 + p1; lsum1 += p2 + p3;
            __nv_bfloat16 h0, h1, h2, h3, l0, l1, l2, l3;
            split1(p0, h0, l0); split1(p1, h1, l1);
            split1(p2, h2, l2); split1(p3, h3, l3);
            int kp = nt >> 1, e = (nt & 1) * 2;
            pah[kp][e] = pkbf(h0, h1); pah[kp][e + 1] = pkbf(h2, h3);
            pal[kp][e] = pkbf(l0, l1); pal[kp][e + 1] = pkbf(l2, l3);
        }

        // O += P V over this 32-key half (3-term); V fragments via ldmatrix.trans
#pragma unroll
        for (int kp = 0; kp < 2; kp++) {
#pragma unroll
            for (int np = 0; np < 4; np++) {
                uint32_t off = SWZ128((uint32_t)((hf * 32 + kp * 16 + vrow) * 128) + np * 32 + vcb);
                uint32_t vh_[4], vl_[4];
                ldsm_x4_t(vh_, st + 16384 + off);   // Vhi
                ldsm_x4_t(vl_, st + 24576 + off);   // Vlo
                mma_bf16(o[2 * np],     pah[kp], vh_);
                mma_bf16(o[2 * np],     pah[kp], vl_);
                mma_bf16(o[2 * np],     pal[kp], vh_);
                mma_bf16(o[2 * np + 1], pah[kp], vh_ + 2);
                mma_bf16(o[2 * np + 1], pah[kp], vl_ + 2);
                mma_bf16(o[2 * np + 1], pal[kp], vh_ + 2);
            }
        }
    }
}

__global__ __launch_bounds__(256, 1) void attn_mma(
    __nv_bfloat16* __restrict__ ohi, __nv_bfloat16* __restrict__ olo)
{
    extern __shared__ char smc[];
    uint32_t sraw = smem_u32(smc);
    uint32_t sb = (sraw + 1023u) & ~1023u;
    char* smb = smc + (sb - sraw);

    const int tid = threadIdx.x, lid = tid & 31, wq = tid >> 5;
    // heavy-first: blockIdx.x = 0 gets the longest (most KV tiles) query block
    const int qi = (gridDim.x - 1) - blockIdx.x;
    const int bh = blockIdx.y;
    const int b = bh >> 4, h = bh & 15;
    const int q0 = qi * 128;
    const size_t base2 = ((size_t)b * Ss * Dd + (size_t)h * DH) * 2;   // bytes

    // Q load (group 0)
#pragma unroll
    for (int i = 0; i < 8; i++) {
        int idx = tid + i * 256;
        int arr = idx >> 10, c = idx & 1023;
        int row = c >> 3; uint32_t colb = (uint32_t)((c & 7) * 16);
        const char* src = (const char*)(arr ? g_qlo : g_qhi) + base2 + (size_t)(q0 + row) * 2048 + colb;
        cp16(sb + A_QZ + arr * 16384 + SWZ128((uint32_t)(row * 128) + colb), src);
    }
    CP_COMMIT();

    const char* kvb[4] = {(const char*)g_khi, (const char*)g_klo,
                          (const char*)g_vhi, (const char*)g_vlo};
    auto kvload = [&](int kt) {
        uint32_t st = sb + (kt % 3) * AT_STG;
        int kv0 = kt * 64;
#pragma unroll
        for (int i = 0; i < 8; i++) {
            int idx = tid + i * 256;
            int arr = idx >> 9, c = idx & 511;
            int row = c >> 3; uint32_t colb = (uint32_t)((c & 7) * 16);
            cp16(st + arr * 8192 + SWZ128((uint32_t)(row * 128) + colb),
                 kvb[arr] + base2 + (size_t)(kv0 + row) * 2048 + colb);
        }
    };

    const int nkt = 2 * qi + 2;
    kvload(0); CP_COMMIT();
    if (nkt > 1) { kvload(1); CP_COMMIT(); }
    CP_WAIT(2);          // Q group done
    __syncthreads();

    // Q fragments -> registers (4 dim-chunks of 16)
    uint32_t qh[4][4], ql[4][4];
    {
        const int a_row = wq * 16 + (lid & 15);
        const uint32_t a_cb = (uint32_t)(((lid >> 4) & 1) * 16);
#pragma unroll
        for (int kd = 0; kd < 4; kd++) {
            uint32_t off = SWZ128((uint32_t)(a_row * 128) + kd * 32 + a_cb);
            ldsm_x4(qh[kd], sb + A_QZ + off);
            ldsm_x4(ql[kd], sb + A_QZ + 16384 + off);
        }
    }

    float o[8][4];
#pragma unroll
    for (int nt = 0; nt < 8; nt++)
#pragma unroll
        for (int e = 0; e < 4; e++) o[nt][e] = 0.f;
    float lsum0 = 0.f, lsum1 = 0.f;

    const int r0g = q0 + wq * 16 + (lid >> 2);
    const int r1g = r0g + 8;
    const int mg = lid >> 3;
    const int krow = (mg >> 1) * 8 + (lid & 7);
    const uint32_t kcb = (uint32_t)((mg & 1) * 16);
    const int vrow = lid & 15;
    const uint32_t vcb = (uint32_t)((lid >> 4) * 16);

    const int ktfull = 2 * qi;     // tiles [0, ktfull) need no mask
    for (int kt = 0; kt < nkt; kt++) {
        if (kt + 2 < nkt) { kvload(kt + 2); CP_COMMIT(); CP_WAIT(2); }
        else if (kt + 1 < nkt) { CP_WAIT(1); }
        else { CP_WAIT(0); }
        __syncthreads();
        uint32_t st = sb + (kt % 3) * AT_STG;
        if (kt < ktfull)
            attn_tile<false>(st, kt * 64, r0g, r1g, lid, krow, kcb, vrow, vcb,
                             qh, ql, o, lsum0, lsum1);
        else
            attn_tile<true>(st, kt * 64, r0g, r1g, lid, krow, kcb, vrow, vcb,
                            qh, ql, o, lsum0, lsum1);
        __syncthreads();
    }

    // lane reduction of lsum (once per kernel, not per tile)
    lsum0 += __shfl_xor_sync(0xffffffffu, lsum0, 1);
    lsum0 += __shfl_xor_sync(0xffffffffu, lsum0, 2);
    lsum1 += __shfl_xor_sync(0xffffffffu, lsum1, 1);
    lsum1 += __shfl_xor_sync(0xffffffffu, lsum1, 2);

    // epilogue: normalize, hi/lo split, stage in smem, coalesced store
    float il0 = 1.f / lsum0, il1 = 1.f / lsum1;
    {
        int rs0 = wq * 16 + (lid >> 2);
#pragma unroll
        for (int nt = 0; nt < 8; nt++) {
            uint32_t colb = (uint32_t)(nt * 16 + (lid & 3) * 4);
            float v0 = o[nt][0] * il0, v1 = o[nt][1] * il0;
            float v2 = o[nt][2] * il1, v3 = o[nt][3] * il1;
            __nv_bfloat16 h0, h1, h2, h3, l0, l1, l2, l3;
            split1(v0, h0, l0); split1(v1, h1, l1);
            split1(v2, h2, l2); split1(v3, h3, l3);
            *(uint32_t*)(smb + A_QZ + rs0 * 128 + colb) = pkbf(h0, h1);
            *(uint32_t*)(smb + A_QZ + (rs0 + 8) * 128 + colb) = pkbf(h2, h3);
            *(uint32_t*)(smb + A_QZ + 16384 + rs0 * 128 + colb) = pkbf(l0, l1);
            *(uint32_t*)(smb + A_QZ + 16384 + (rs0 + 8) * 128 + colb) = pkbf(l2, l3);
        }
    }
    __syncthreads();
#pragma unroll
    for (int i = 0; i < 8; i++) {
        int idx = tid + i * 256;
        int arr = idx >> 10, c = idx & 1023;
        int row = c >> 3; uint32_t colb = (uint32_t)((c & 7) * 16);
        uint4 v = *(uint4*)(smb + A_QZ + arr * 16384 + row * 128 + colb);
        char* dst = (char*)(arr ? olo : ohi) + base2 + (size_t)(q0 + row) * 2048 + colb;
        *(uint4*)dst = v;
    }
}

// ---------------- launch ----------------
extern "C" void kernel_launch(void* const* d_in, const int* in_sizes, int n_in,
                              void* d_out, int out_size)
{
    const float* x  = (const float*)d_in[0];
    const float* Wq = (const float*)d_in[1];
    const float* bq = (const float*)d_in[2];
    const float* Wk = (const float*)d_in[3];
    const float* bk = (const float*)d_in[4];
    const float* Wv = (const float*)d_in[5];
    const float* bv = (const float*)d_in[6];
    const float* Wo = (const float*)d_in[7];
    const float* bo = (const float*)d_in[8];
    float* out = (float*)d_out;

    __nv_bfloat16 *xhi, *xlo, *ahi, *alo, *wthi, *wtlo;
    cudaGetSymbolAddress((void**)&xhi,  g_xhi);
    cudaGetSymbolAddress((void**)&xlo,  g_xlo);
    cudaGetSymbolAddress((void**)&ahi,  g_ahi);
    cudaGetSymbolAddress((void**)&alo,  g_alo);
    cudaGetSymbolAddress((void**)&wthi, g_wthi);
    cudaGetSymbolAddress((void**)&wtlo, g_wtlo);

    cudaFuncSetAttribute(gemm_mma<0>,
                         cudaFuncAttributeMaxDynamicSharedMemorySize, GEMM_SMEM);
    cudaFuncSetAttribute(gemm_mma<1>,
                         cudaFuncAttributeMaxDynamicSharedMemorySize, GEMM_SMEM);
    cudaFuncSetAttribute(attn_mma,
                         cudaFuncAttributeMaxDynamicSharedMemorySize, ATT_SMEM);

    transpose_split<<<dim3(32, 32, 4), dim3(32, 8)>>>(Wq, Wk, Wv, Wo, wthi, wtlo);
    split_f32<<<(MM * Dd) / 1024, 256>>>(x, xhi, xlo);

    // Fused QKV projection: one launch, outputs routed to separate q/k/v buffers
    gemm_mma<0><<<dim3(24, MM / BM), 256, GEMM_SMEM>>>(bq, bk, bv, nullptr);

    attn_mma<<<dim3(Ss / 128, Bb * Hh), 256, ATT_SMEM>>>(ahi, alo);

    // Output projection
    gemm_mma<1><<<dim3(8, MM / BM), 256, GEMM_SMEM>>>(bo, nullptr, nullptr, out);
}

// round 11
// speedup vs baseline: 1.3227x; 1.2246x over previous
#include <cuda_runtime.h>
#include <cuda_bf16.h>
#include <cuda_fp16.h>
#include <math.h>
#include <stdint.h>

// Problem constants
constexpr int Bb = 2, Ss = 2048, Dd = 1024, Hh = 16, DH = 64;
constexpr int MM = Bb * Ss;       // 4096 rows

// ---------------- scratch (no cudaMalloc allowed) ----------------
__device__ __nv_bfloat16 g_xhi[MM * Dd];
__device__ __nv_bfloat16 g_xlo[MM * Dd];
__device__ __half g_qhi[MM * Dd];     // Q: fp16 hi/lo
__device__ __half g_qlo[MM * Dd];
__device__ __half g_k16[MM * Dd];     // K: single fp16
__device__ __half g_v16[MM * Dd];     // V: single fp16
__device__ __nv_bfloat16 g_ahi[MM * Dd];
__device__ __nv_bfloat16 g_alo[MM * Dd];
__device__ __nv_bfloat16 g_wthi[4 * Dd * Dd];    // transposed weights [N,K], Wq|Wk|Wv|Wo
__device__ __nv_bfloat16 g_wtlo[4 * Dd * Dd];

// ================= helpers =================
__device__ __forceinline__ uint32_t smem_u32(const void* p) {
    uint32_t a;
    asm("{ .reg .u64 t; cvta.to.shared.u64 t, %1; cvt.u32.u64 %0, t; }" : "=r"(a) : "l"(p));
    return a;
}
__device__ __forceinline__ void ldsm_x4(uint32_t* r, uint32_t a) {
    asm volatile("ldmatrix.sync.aligned.m8n8.x4.shared.b16 {%0,%1,%2,%3}, [%4];"
                 : "=r"(r[0]), "=r"(r[1]), "=r"(r[2]), "=r"(r[3]) : "r"(a));
}
__device__ __forceinline__ void ldsm_x4_t(uint32_t* r, uint32_t a) {
    asm volatile("ldmatrix.sync.aligned.m8n8.x4.trans.shared.b16 {%0,%1,%2,%3}, [%4];"
                 : "=r"(r[0]), "=r"(r[1]), "=r"(r[2]), "=r"(r[3]) : "r"(a));
}
__device__ __forceinline__ void mma_bf16(float* c, const uint32_t* a, const uint32_t* b) {
    asm volatile("mma.sync.aligned.m16n8k16.row.col.f32.bf16.bf16.f32 "
                 "{%0,%1,%2,%3}, {%4,%5,%6,%7}, {%8,%9}, {%0,%1,%2,%3};"
                 : "+f"(c[0]), "+f"(c[1]), "+f"(c[2]), "+f"(c[3])
                 : "r"(a[0]), "r"(a[1]), "r"(a[2]), "r"(a[3]), "r"(b[0]), "r"(b[1]));
}
__device__ __forceinline__ void mma_f16(float* c, const uint32_t* a, const uint32_t* b) {
    asm volatile("mma.sync.aligned.m16n8k16.row.col.f32.f16.f16.f32 "
                 "{%0,%1,%2,%3}, {%4,%5,%6,%7}, {%8,%9}, {%0,%1,%2,%3};"
                 : "+f"(c[0]), "+f"(c[1]), "+f"(c[2]), "+f"(c[3])
                 : "r"(a[0]), "r"(a[1]), "r"(a[2]), "r"(a[3]), "r"(b[0]), "r"(b[1]));
}
__device__ __forceinline__ void cp16(uint32_t dst, const void* src) {
    asm volatile("cp.async.cg.shared.global [%0], [%1], 16;" :: "r"(dst), "l"(src));
}
#define CP_COMMIT() asm volatile("cp.async.commit_group;" ::: "memory")
#define CP_WAIT(n)  asm volatile("cp.async.wait_group %0;" :: "n"(n) : "memory")
#define SWZ128(off) ((off) ^ (((off) >> 3) & 0x70))

__device__ __forceinline__ void split1(float x, __nv_bfloat16& h, __nv_bfloat16& l) {
    h = __float2bfloat16(x);
    l = __float2bfloat16(x - __bfloat162float(h));
}
__device__ __forceinline__ uint32_t pkbf(__nv_bfloat16 a, __nv_bfloat16 b) {
    uint16_t ua = *(uint16_t*)&a, ub = *(uint16_t*)&b;
    return (uint32_t)ua | ((uint32_t)ub << 16);
}
__device__ __forceinline__ uint32_t pkh2(float a, float b) {
    __half2 h = __floats2half2_rn(a, b);
    return *(uint32_t*)&h;
}
__device__ __forceinline__ void split1h(float x, float& hf, uint16_t& hbits) {
    __half h = __float2half_rn(x);
    hf = __half2float(h);
    hbits = *(uint16_t*)&h;
}

// ================= split kernels =================
__global__ __launch_bounds__(256) void split_f32(
    const float* __restrict__ in, __nv_bfloat16* __restrict__ hi,
    __nv_bfloat16* __restrict__ lo)
{
    int i = blockIdx.x * 256 + threadIdx.x;
    float4 v = ((const float4*)in)[i];
    __nv_bfloat16 h0, h1, h2, h3, l0, l1, l2, l3;
    split1(v.x, h0, l0); split1(v.y, h1, l1); split1(v.z, h2, l2); split1(v.w, h3, l3);
    uint2 hp, lp;
    hp.x = pkbf(h0, h1); hp.y = pkbf(h2, h3);
    lp.x = pkbf(l0, l1); lp.y = pkbf(l2, l3);
    ((uint2*)hi)[i] = hp;
    ((uint2*)lo)[i] = lp;
}

// transpose W [K,N] -> Wt [N,K] bf16 hi/lo, for 4 weights (blockIdx.z)
__global__ __launch_bounds__(256) void transpose_split(
    const float* __restrict__ W0, const float* __restrict__ W1,
    const float* __restrict__ W2, const float* __restrict__ W3,
    __nv_bfloat16* __restrict__ hi, __nv_bfloat16* __restrict__ lo)
{
    __shared__ float sm[32][33];
    const float* W = (blockIdx.z == 0) ? W0 : (blockIdx.z == 1) ? W1 : (blockIdx.z == 2) ? W2 : W3;
    const int tx = threadIdx.x, ty = threadIdx.y;
    const int k0 = blockIdx.y * 32, n0 = blockIdx.x * 32;
#pragma unroll
    for (int i = 0; i < 4; i++)
        sm[ty + 8 * i][tx] = W[(size_t)(k0 + ty + 8 * i) * Dd + n0 + tx];
    __syncthreads();
    size_t zb = (size_t)blockIdx.z * Dd * Dd;
#pragma unroll
    for (int i = 0; i < 4; i++) {
        float v = sm[tx][ty + 8 * i];
        __nv_bfloat16 h, l; split1(v, h, l);
        size_t o = zb + (size_t)(n0 + ty + 8 * i) * Dd + k0 + tx;
        hi[o] = h; lo[o] = l;
    }
}

// ================= mma.sync GEMM (256 threads, bf16 3-term internals) =================
// MODE 0: QKV. z = blockIdx.x>>3: z==0 -> Q fp16 hi/lo; z==1 -> K fp16; z==2 -> V fp16.
// MODE 1: O projection, fp32 output.
constexpr int BM = 128, BN = 128, BKC = 64;
constexpr int STG_BYTES = 65536;
constexpr int OFF_AHI = 0, OFF_ALO = 16384, OFF_BHI = 32768, OFF_BLO = 49152;
constexpr int GEMM_SMEM = 2 * STG_BYTES + 1024;

template<int MODE>
__global__ __launch_bounds__(256, 1) void gemm_mma(
    const float* __restrict__ bias0, const float* __restrict__ bias1,
    const float* __restrict__ bias2, float* __restrict__ C)
{
    extern __shared__ char smc[];
    uint32_t sraw = smem_u32(smc);
    uint32_t sb = (sraw + 1023u) & ~1023u;

    const int tid = threadIdx.x, lid = tid & 31, wid = tid >> 5;
    const int wm = wid >> 2, wn = wid & 3;
    const int m0 = blockIdx.y * BM;
    const int z = (MODE == 0) ? (blockIdx.x >> 3) : 3;
    const int n0 = (MODE == 0) ? ((blockIdx.x & 7) * BN) : (blockIdx.x * BN);

    const __nv_bfloat16* Ahi = (MODE == 0) ? g_xhi : g_ahi;
    const __nv_bfloat16* Alo = (MODE == 0) ? g_xlo : g_alo;
    const __nv_bfloat16* Bhi = g_wthi + (size_t)z * Dd * Dd;
    const __nv_bfloat16* Blo = g_wtlo + (size_t)z * Dd * Dd;
    const float* bias = (MODE == 1) ? bias0 : ((z == 0) ? bias0 : (z == 1) ? bias1 : bias2);

    uint32_t dsto[4];
    int rowA[4], rowB[4];
    uint32_t coff[4];
#pragma unroll
    for (int i = 0; i < 4; i++) {
        int idx = tid + i * 256;
        int r = idx >> 3;
        uint32_t off = (uint32_t)(r * 128 + (idx & 7) * 16);
        dsto[i] = SWZ128(off);
        rowA[i] = m0 + r;
        rowB[i] = n0 + r;
        coff[i] = (uint32_t)((idx & 7) * 16);
    }

    auto prefetch = [&](int chunk, int s) {
        uint32_t st = sb + s * STG_BYTES;
        size_t kb = (size_t)chunk * BKC * 2;
#pragma unroll
        for (int i = 0; i < 4; i++) {
            size_t ga = (size_t)rowA[i] * (Dd * 2) + kb + coff[i];
            size_t gb = (size_t)rowB[i] * (Dd * 2) + kb + coff[i];
            cp16(st + OFF_AHI + dsto[i], (const char*)Ahi + ga);
            cp16(st + OFF_ALO + dsto[i], (const char*)Alo + ga);
            cp16(st + OFF_BHI + dsto[i], (const char*)Bhi + gb);
            cp16(st + OFF_BLO + dsto[i], (const char*)Blo + gb);
        }
    };

    float acc[4][4][4];
#pragma unroll
    for (int mt = 0; mt < 4; mt++)
#pragma unroll
        for (int nt = 0; nt < 4; nt++)
#pragma unroll
            for (int e = 0; e < 4; e++) acc[mt][nt][e] = 0.f;

    prefetch(0, 0);
    CP_COMMIT();

    const int a_row = wm * 64 + (lid & 15);
    const uint32_t a_cb = (uint32_t)(((lid >> 4) & 1) * 16);
    const int mg = lid >> 3;
    const int b_row0 = wn * 32 + (mg >> 1) * 8 + (lid & 7);
    const uint32_t b_cb = (uint32_t)((mg & 1) * 16);

    const int NIT = Dd / BKC;   // 16
    for (int it = 0; it < NIT; it++) {
        const int s = it & 1;
        if (it + 1 < NIT) {
            prefetch(it + 1, (it + 1) & 1);
            CP_COMMIT();
            CP_WAIT(1);
        } else {
            CP_WAIT(0);
        }
        __syncthreads();

        uint32_t st = sb + s * STG_BYTES;
#pragma unroll
        for (int kt = 0; kt < 4; kt++) {
            uint32_t ah[4][4], al[4][4];
#pragma unroll
            for (int mt = 0; mt < 4; mt++) {
                uint32_t off = (uint32_t)((a_row + mt * 16) * 128) + kt * 32 + a_cb;
                off = SWZ128(off);
                ldsm_x4(ah[mt], st + OFF_AHI + off);
                ldsm_x4(al[mt], st + OFF_ALO + off);
            }
            uint32_t bh[4][2], bl[4][2];
#pragma unroll
            for (int p = 0; p < 2; p++) {
                uint32_t off = (uint32_t)((b_row0 + p * 16) * 128) + kt * 32 + b_cb;
                off = SWZ128(off);
                uint32_t r[4];
                ldsm_x4(r, st + OFF_BHI + off);
                bh[2 * p][0] = r[0]; bh[2 * p][1] = r[1];
                bh[2 * p + 1][0] = r[2]; bh[2 * p + 1][1] = r[3];
                ldsm_x4(r, st + OFF_BLO + off);
                bl[2 * p][0] = r[0]; bl[2 * p][1] = r[1];
                bl[2 * p + 1][0] = r[2]; bl[2 * p + 1][1] = r[3];
            }
#pragma unroll
            for (int mt = 0; mt < 4; mt++)
#pragma unroll
                for (int nt = 0; nt < 4; nt++) {
                    mma_bf16(acc[mt][nt], ah[mt], bh[nt]);
                    mma_bf16(acc[mt][nt], ah[mt], bl[nt]);
                    mma_bf16(acc[mt][nt], al[mt], bh[nt]);
                }
        }
        __syncthreads();
    }

    // epilogue
#pragma unroll
    for (int nt = 0; nt < 4; nt++) {
        int c0 = n0 + wn * 32 + nt * 8 + (lid & 3) * 2;
        float b0 = bias[c0], b1 = bias[c0 + 1];
#pragma unroll
        for (int mt = 0; mt < 4; mt++) {
            int r0 = m0 + wm * 64 + mt * 16 + (lid >> 2);
            float v0 = acc[mt][nt][0] + b0, v1 = acc[mt][nt][1] + b1;
            float v2 = acc[mt][nt][2] + b0, v3 = acc[mt][nt][3] + b1;
            if (MODE == 0) {
                if (z == 0) {
                    // Q: fp16 hi/lo
                    float h0f, h1f, h2f, h3f;
                    uint16_t h0, h1, h2, h3;
                    split1h(v0, h0f, h0); split1h(v1, h1f, h1);
                    split1h(v2, h2f, h2); split1h(v3, h3f, h3);
                    *(uint32_t*)&g_qhi[(size_t)r0 * Dd + c0] = (uint32_t)h0 | ((uint32_t)h1 << 16);
                    *(uint32_t*)&g_qlo[(size_t)r0 * Dd + c0] = pkh2(v0 - h0f, v1 - h1f);
                    *(uint32_t*)&g_qhi[(size_t)(r0 + 8) * Dd + c0] = (uint32_t)h2 | ((uint32_t)h3 << 16);
                    *(uint32_t*)&g_qlo[(size_t)(r0 + 8) * Dd + c0] = pkh2(v2 - h2f, v3 - h3f);
                } else {
                    // K/V: single fp16
                    __half* dst = (z == 1) ? g_k16 : g_v16;
                    *(uint32_t*)&dst[(size_t)r0 * Dd + c0] = pkh2(v0, v1);
                    *(uint32_t*)&dst[(size_t)(r0 + 8) * Dd + c0] = pkh2(v2, v3);
                }
            } else {
                float2 w0 = {v0, v1}, w1 = {v2, v3};
                *(float2*)&C[(size_t)r0 * Dd + c0] = w0;
                *(float2*)&C[(size_t)(r0 + 8) * Dd + c0] = w1;
            }
        }
    }
}

// ================= Flash attention (fp16, causal, max-free softmax) =================
// K,V single fp16; Q fp16 hi/lo (2-MMA QK); P single fp16 (1-MMA PV).
// Max-free streaming softmax in exp2 domain; per-thread lsum, reduced at end.
constexpr int AT_STG = 16384;                      // K 8KB | V 8KB
constexpr int A_QZ = 3 * AT_STG;                   // Q hi 16K + lo 16K (reused for out staging)
constexpr int ATT_SMEM = A_QZ + 32768 + 1024;
constexpr float SCL2 = 0.03125f * 1.4426950408889634f;   // (1/32) * log2(e)

template<bool MASK>
__device__ __forceinline__ void attn_tile(
    uint32_t st, int kv0, int r0g, int r1g, int lid,
    int krow, uint32_t kcb, int vrow, uint32_t vcb,
    const uint32_t (&qh)[4][4], const uint32_t (&ql)[4][4],
    float (&o)[8][4], float& lsum0, float& lsum1)
{
#pragma unroll
    for (int hf = 0; hf < 2; hf++) {
        // S = Q K^T over 32 keys: Qhi*K + Qlo*K (K rounding ~2^-12, corrected Q)
        float s[4][4];
#pragma unroll
        for (int nt = 0; nt < 4; nt++)
#pragma unroll
            for (int e = 0; e < 4; e++) s[nt][e] = 0.f;
#pragma unroll
        for (int kd = 0; kd < 4; kd++) {
#pragma unroll
            for (int np = 0; np < 2; np++) {
                uint32_t off = SWZ128((uint32_t)((hf * 32 + np * 16 + krow) * 128) + kd * 32 + kcb);
                uint32_t kh_[4];
                ldsm_x4(kh_, st + off);            // K fp16
                mma_f16(s[2 * np],     qh[kd], kh_);
                mma_f16(s[2 * np],     ql[kd], kh_);
                mma_f16(s[2 * np + 1], qh[kd], kh_ + 2);
                mma_f16(s[2 * np + 1], ql[kd], kh_ + 2);
            }
        }

        // P = 2^(scale*S) (no max shift), pack to single fp16 A-fragments
        uint32_t pa[2][4];
#pragma unroll
        for (int nt = 0; nt < 4; nt++) {
            float v0, v1, v2, v3;
            if (MASK) {
                int kg = kv0 + hf * 32 + nt * 8 + (lid & 3) * 2;
                v0 = (kg     <= r0g) ? s[nt][0] * SCL2 : -INFINITY;
                v1 = (kg + 1 <= r0g) ? s[nt][1] * SCL2 : -INFINITY;
                v2 = (kg     <= r1g) ? s[nt][2] * SCL2 : -INFINITY;
                v3 = (kg + 1 <= r1g) ? s[nt][3] * SCL2 : -INFINITY;
            } else {
                v0 = s[nt][0] * SCL2; v1 = s[nt][1] * SCL2;
                v2 = s[nt][2] * SCL2; v3 = s[nt][3] * SCL2;
            }
            float p0 = exp2f(v0), p1 = exp2f(v1);
            float p2 = exp2f(v2), p3 = exp2f(v3);
            lsum0 += p0 + p1; lsum1 += p2 + p3;
            int kp = nt >> 1, e = (nt & 1) * 2;
            pa[kp][e]     = pkh2(p0, p1);
            pa[kp][e + 1] = pkh2(p2, p3);
        }

        // O += P V over this 32-key half (1 MMA per n-tile)
#pragma unroll
        for (int kp = 0; kp < 2; kp++) {
#pragma unroll
            for (int np = 0; np < 4; np++) {
                uint32_t off = SWZ128((uint32_t)((hf * 32 + kp * 16 + vrow) * 128) + np * 32 + vcb);
                uint32_t vh_[4];
                ldsm_x4_t(vh_, st + 8192 + off);   // V fp16
                mma_f16(o[2 * np],     pa[kp], vh_);
                mma_f16(o[2 * np + 1], pa[kp], vh_ + 2);
            }
        }
    }
}

__global__ __launch_bounds__(256, 1) void attn_mma(
    __nv_bfloat16* __restrict__ ohi, __nv_bfloat16* __restrict__ olo)
{
    extern __shared__ char smc[];
    uint32_t sraw = smem_u32(smc);
    uint32_t sb = (sraw + 1023u) & ~1023u;
    char* smb = smc + (sb - sraw);

    const int tid = threadIdx.x, lid = tid & 31, wq = tid >> 5;
    // heavy-first: blockIdx.x = 0 gets the longest (most KV tiles) query block
    const int qi = (gridDim.x - 1) - blockIdx.x;
    const int bh = blockIdx.y;
    const int b = bh >> 4, h = bh & 15;
    const int q0 = qi * 128;
    const size_t base2 = ((size_t)b * Ss * Dd + (size_t)h * DH) * 2;   // bytes

    // Q load: fp16 hi/lo, 128 rows x 128B each
#pragma unroll
    for (int i = 0; i < 8; i++) {
        int idx = tid + i * 256;
        int arr = idx >> 10, c = idx & 1023;
        int row = c >> 3; uint32_t colb = (uint32_t)((c & 7) * 16);
        const char* src = (const char*)(arr ? g_qlo : g_qhi) + base2 + (size_t)(q0 + row) * 2048 + colb;
        cp16(sb + A_QZ + arr * 16384 + SWZ128((uint32_t)(row * 128) + colb), src);
    }
    CP_COMMIT();

    const char* kvb[2] = {(const char*)g_k16, (const char*)g_v16};
    auto kvload = [&](int kt) {
        uint32_t st = sb + (kt % 3) * AT_STG;
        int kv0 = kt * 64;
#pragma unroll
        for (int i = 0; i < 4; i++) {
            int idx = tid + i * 256;
            int arr = idx >> 9, c = idx & 511;
            int row = c >> 3; uint32_t colb = (uint32_t)((c & 7) * 16);
            cp16(st + arr * 8192 + SWZ128((uint32_t)(row * 128) + colb),
                 kvb[arr] + base2 + (size_t)(kv0 + row) * 2048 + colb);
        }
    };

    const int nkt = 2 * qi + 2;
    kvload(0); CP_COMMIT();
    if (nkt > 1) { kvload(1); CP_COMMIT(); }
    CP_WAIT(2);          // Q group done
    __syncthreads();

    // Q fragments -> registers (4 dim-chunks of 16)
    uint32_t qh[4][4], ql[4][4];
    {
        const int a_row = wq * 16 + (lid & 15);
        const uint32_t a_cb = (uint32_t)(((lid >> 4) & 1) * 16);
#pragma unroll
        for (int kd = 0; kd < 4; kd++) {
            uint32_t off = SWZ128((uint32_t)(a_row * 128) + kd * 32 + a_cb);
            ldsm_x4(qh[kd], sb + A_QZ + off);
            ldsm_x4(ql[kd], sb + A_QZ + 16384 + off);
        }
    }

    float o[8][4];
#pragma unroll
    for (int nt = 0; nt < 8; nt++)
#pragma unroll
        for (int e = 0; e < 4; e++) o[nt][e] = 0.f;
    float lsum0 = 0.f, lsum1 = 0.f;

    const int r0g = q0 + wq * 16 + (lid >> 2);
    const int r1g = r0g + 8;
    const int mg = lid >> 3;
    const int krow = (mg >> 1) * 8 + (lid & 7);
    const uint32_t kcb = (uint32_t)((mg & 1) * 16);
    const int vrow = lid & 15;
    const uint32_t vcb = (uint32_t)((lid >> 4) * 16);

    const int ktfull = 2 * qi;     // tiles [0, ktfull) need no mask
    for (int kt = 0; kt < nkt; kt++) {
        if (kt + 2 < nkt) { kvload(kt + 2); CP_COMMIT(); CP_WAIT(2); }
        else if (kt + 1 < nkt) { CP_WAIT(1); }
        else { CP_WAIT(0); }
        __syncthreads();
        uint32_t st = sb + (kt % 3) * AT_STG;
        if (kt < ktfull)
            attn_tile<false>(st, kt * 64, r0g, r1g, lid, krow, kcb, vrow, vcb,
                             qh, ql, o, lsum0, lsum1);
        else
            attn_tile<true>(st, kt * 64, r0g, r1g, lid, krow, kcb, vrow, vcb,
                            qh, ql, o, lsum0, lsum1);
        __syncthreads();
    }

    // lane reduction of lsum (once per kernel, not per tile)
    lsum0 += __shfl_xor_sync(0xffffffffu, lsum0, 1);
    lsum0 += __shfl_xor_sync(0xffffffffu, lsum0, 2);
    lsum1 += __shfl_xor_sync(0xffffffffu, lsum1, 1);
    lsum1 += __shfl_xor_sync(0xffffffffu, lsum1, 2);

    // epilogue: normalize, bf16 hi/lo split, stage in smem, coalesced store
    float il0 = 1.f / lsum0, il1 = 1.f / lsum1;
    {
        int rs0 = wq * 16 + (lid >> 2);
#pragma unroll
        for (int nt = 0; nt < 8; nt++) {
            uint32_t colb = (uint32_t)(nt * 16 + (lid & 3) * 4);
            float v0 = o[nt][0] * il0, v1 = o[nt][1] * il0;
            float v2 = o[nt][2] * il1, v3 = o[nt][3] * il1;
            __nv_bfloat16 h0, h1, h2, h3, l0, l1, l2, l3;
            split1(v0, h0, l0); split1(v1, h1, l1);
            split1(v2, h2, l2); split1(v3, h3, l3);
            *(uint32_t*)(smb + A_QZ + rs0 * 128 + colb) = pkbf(h0, h1);
            *(uint32_t*)(smb + A_QZ + (rs0 + 8) * 128 + colb) = pkbf(h2, h3);
            *(uint32_t*)(smb + A_QZ + 16384 + rs0 * 128 + colb) = pkbf(l0, l1);
            *(uint32_t*)(smb + A_QZ + 16384 + (rs0 + 8) * 128 + colb) = pkbf(l2, l3);
        }
    }
    __syncthreads();
#pragma unroll
    for (int i = 0; i < 8; i++) {
        int idx = tid + i * 256;
        int arr = idx >> 10, c = idx & 1023;
        int row = c >> 3; uint32_t colb = (uint32_t)((c & 7) * 16);
        uint4 v = *(uint4*)(smb + A_QZ + arr * 16384 + row * 128 + colb);
        char* dst = (char*)(arr ? olo : ohi) + base2 + (size_t)(q0 + row) * 2048 + colb;
        *(uint4*)dst = v;
    }
}

// ---------------- launch ----------------
extern "C" void kernel_launch(void* const* d_in, const int* in_sizes, int n_in,
                              void* d_out, int out_size)
{
    const float* x  = (const float*)d_in[0];
    const float* Wq = (const float*)d_in[1];
    const float* bq = (const float*)d_in[2];
    const float* Wk = (const float*)d_in[3];
    const float* bk = (const float*)d_in[4];
    const float* Wv = (const float*)d_in[5];
    const float* bv = (const float*)d_in[6];
    const float* Wo = (const float*)d_in[7];
    const float* bo = (const float*)d_in[8];
    float* out = (float*)d_out;

    __nv_bfloat16 *xhi, *xlo, *ahi, *alo, *wthi, *wtlo;
    cudaGetSymbolAddress((void**)&xhi,  g_xhi);
    cudaGetSymbolAddress((void**)&xlo,  g_xlo);
    cudaGetSymbolAddress((void**)&ahi,  g_ahi);
    cudaGetSymbolAddress((void**)&alo,  g_alo);
    cudaGetSymbolAddress((void**)&wthi, g_wthi);
    cudaGetSymbolAddress((void**)&wtlo, g_wtlo);

    cudaFuncSetAttribute(gemm_mma<0>,
                         cudaFuncAttributeMaxDynamicSharedMemorySize, GEMM_SMEM);
    cudaFuncSetAttribute(gemm_mma<1>,
                         cudaFuncAttributeMaxDynamicSharedMemorySize, GEMM_SMEM);
    cudaFuncSetAttribute(attn_mma,
                         cudaFuncAttributeMaxDynamicSharedMemorySize, ATT_SMEM);

    transpose_split<<<dim3(32, 32, 4), dim3(32, 8)>>>(Wq, Wk, Wv, Wo, wthi, wtlo);
    split_f32<<<(MM * Dd) / 1024, 256>>>(x, xhi, xlo);

    // Fused QKV projection: one launch, outputs routed to q(hi/lo fp16), k16, v16
    gemm_mma<0><<<dim3(24, MM / BM), 256, GEMM_SMEM>>>(bq, bk, bv, nullptr);

    attn_mma<<<dim3(Ss / 128, Bb * Hh), 256, ATT_SMEM>>>(ahi, alo);

    // Output projection
    gemm_mma<1><<<dim3(8, MM / BM), 256, GEMM_SMEM>>>(bo, nullptr, nullptr, out);
}

// round 12
// speedup vs baseline: 2.6998x; 2.0411x over previous
#include <cuda_runtime.h>
#include <cuda_fp16.h>
#include <math.h>
#include <stdint.h>

// Problem constants
constexpr int Bb = 2, Ss = 2048, Dd = 1024, Hh = 16, DH = 64;
constexpr int MM = Bb * Ss;       // 4096 rows

// ---------------- scratch (no cudaMalloc allowed) ----------------
__device__ __half g_x16[MM * Dd];
__device__ __half g_q16[MM * Dd];
__device__ __half g_k16[MM * Dd];
__device__ __half g_v16[MM * Dd];
__device__ __half g_a16[MM * Dd];
__device__ __half g_wt16[4 * Dd * Dd];    // transposed weights [N,K], Wq|Wk|Wv|Wo

// ================= helpers =================
__device__ __forceinline__ uint32_t smem_u32(const void* p) {
    uint32_t a;
    asm("{ .reg .u64 t; cvta.to.shared.u64 t, %1; cvt.u32.u64 %0, t; }" : "=r"(a) : "l"(p));
    return a;
}
__device__ __forceinline__ void ldsm_x4(uint32_t* r, uint32_t a) {
    asm volatile("ldmatrix.sync.aligned.m8n8.x4.shared.b16 {%0,%1,%2,%3}, [%4];"
                 : "=r"(r[0]), "=r"(r[1]), "=r"(r[2]), "=r"(r[3]) : "r"(a));
}
__device__ __forceinline__ void ldsm_x4_t(uint32_t* r, uint32_t a) {
    asm volatile("ldmatrix.sync.aligned.m8n8.x4.trans.shared.b16 {%0,%1,%2,%3}, [%4];"
                 : "=r"(r[0]), "=r"(r[1]), "=r"(r[2]), "=r"(r[3]) : "r"(a));
}
__device__ __forceinline__ void mma_f16(float* c, const uint32_t* a, const uint32_t* b) {
    asm volatile("mma.sync.aligned.m16n8k16.row.col.f32.f16.f16.f32 "
                 "{%0,%1,%2,%3}, {%4,%5,%6,%7}, {%8,%9}, {%0,%1,%2,%3};"
                 : "+f"(c[0]), "+f"(c[1]), "+f"(c[2]), "+f"(c[3])
                 : "r"(a[0]), "r"(a[1]), "r"(a[2]), "r"(a[3]), "r"(b[0]), "r"(b[1]));
}
__device__ __forceinline__ void cp16(uint32_t dst, const void* src) {
    asm volatile("cp.async.cg.shared.global [%0], [%1], 16;" :: "r"(dst), "l"(src));
}
#define CP_COMMIT() asm volatile("cp.async.commit_group;" ::: "memory")
#define CP_WAIT(n)  asm volatile("cp.async.wait_group %0;" :: "n"(n) : "memory")
#define SWZ128(off) ((off) ^ (((off) >> 3) & 0x70))

__device__ __forceinline__ uint32_t pkh2(float a, float b) {
    __half2 h = __floats2half2_rn(a, b);
    return *(uint32_t*)&h;
}

// ================= prep kernels =================
__global__ __launch_bounds__(256) void cvt_f16(
    const float* __restrict__ in, __half* __restrict__ out)
{
    int i = blockIdx.x * 256 + threadIdx.x;      // float4 index
    float4 v = ((const float4*)in)[i];
    uint2 p;
    p.x = pkh2(v.x, v.y);
    p.y = pkh2(v.z, v.w);
    ((uint2*)out)[i] = p;
}

// transpose W [K,N] -> Wt [N,K] fp16, for 4 weights (blockIdx.z)
__global__ __launch_bounds__(256) void transpose_cvt(
    const float* __restrict__ W0, const float* __restrict__ W1,
    const float* __restrict__ W2, const float* __restrict__ W3,
    __half* __restrict__ out)
{
    __shared__ float sm[32][33];
    const float* W = (blockIdx.z == 0) ? W0 : (blockIdx.z == 1) ? W1 : (blockIdx.z == 2) ? W2 : W3;
    const int tx = threadIdx.x, ty = threadIdx.y;
    const int k0 = blockIdx.y * 32, n0 = blockIdx.x * 32;
#pragma unroll
    for (int i = 0; i < 4; i++)
        sm[ty + 8 * i][tx] = W[(size_t)(k0 + ty + 8 * i) * Dd + n0 + tx];
    __syncthreads();
    size_t zb = (size_t)blockIdx.z * Dd * Dd;
#pragma unroll
    for (int i = 0; i < 4; i++) {
        float v = sm[tx][ty + 8 * i];
        out[zb + (size_t)(n0 + ty + 8 * i) * Dd + k0 + tx] = __float2half_rn(v);
    }
}

// ================= mma.sync GEMM (fp16 single, 1 MMA) =================
// MODE 0: QKV. grid (24, 32); z = blockIdx.x>>3 -> q16/k16/v16 outputs.
// MODE 1: O projection. grid (8, 32); fp32 output to C.
// CTA tile 128x128, BK=64, double-buffered cp.async.
// 8 warps: grid 2(m) x 4(n), warp tile 64x32 -> 4 m16 x 4 n8 mma tiles.
constexpr int BM = 128, BN = 128, BKC = 64;
constexpr int STG_BYTES = 32768;               // A 16K | B 16K
constexpr int OFF_A = 0, OFF_B = 16384;
constexpr int GEMM_SMEM = 2 * STG_BYTES + 1024;

template<int MODE>
__global__ __launch_bounds__(256, 2) void gemm_mma(
    const float* __restrict__ bias0, const float* __restrict__ bias1,
    const float* __restrict__ bias2, float* __restrict__ C)
{
    extern __shared__ char smc[];
    uint32_t sraw = smem_u32(smc);
    uint32_t sb = (sraw + 1023u) & ~1023u;

    const int tid = threadIdx.x, lid = tid & 31, wid = tid >> 5;
    const int wm = wid >> 2, wn = wid & 3;
    const int m0 = blockIdx.y * BM;
    const int z = (MODE == 0) ? (blockIdx.x >> 3) : 3;
    const int n0 = (MODE == 0) ? ((blockIdx.x & 7) * BN) : (blockIdx.x * BN);

    const __half* A = (MODE == 0) ? g_x16 : g_a16;
    const __half* B = g_wt16 + (size_t)z * Dd * Dd;
    const float* bias = (MODE == 1) ? bias0 : ((z == 0) ? bias0 : (z == 1) ? bias1 : bias2);
    __half* Cq = nullptr;
    if (MODE == 0) Cq = (z == 0) ? g_q16 : (z == 1) ? g_k16 : g_v16;

    uint32_t dsto[4];
    int rowA[4], rowB[4];
    uint32_t coff[4];
#pragma unroll
    for (int i = 0; i < 4; i++) {
        int idx = tid + i * 256;
        int r = idx >> 3;
        uint32_t off = (uint32_t)(r * 128 + (idx & 7) * 16);
        dsto[i] = SWZ128(off);
        rowA[i] = m0 + r;
        rowB[i] = n0 + r;
        coff[i] = (uint32_t)((idx & 7) * 16);
    }

    auto prefetch = [&](int chunk, int s) {
        uint32_t st = sb + s * STG_BYTES;
        size_t kb = (size_t)chunk * BKC * 2;
#pragma unroll
        for (int i = 0; i < 4; i++) {
            size_t ga = (size_t)rowA[i] * (Dd * 2) + kb + coff[i];
            size_t gb = (size_t)rowB[i] * (Dd * 2) + kb + coff[i];
            cp16(st + OFF_A + dsto[i], (const char*)A + ga);
            cp16(st + OFF_B + dsto[i], (const char*)B + gb);
        }
    };

    float acc[4][4][4];
#pragma unroll
    for (int mt = 0; mt < 4; mt++)
#pragma unroll
        for (int nt = 0; nt < 4; nt++)
#pragma unroll
            for (int e = 0; e < 4; e++) acc[mt][nt][e] = 0.f;

    prefetch(0, 0);
    CP_COMMIT();

    const int a_row = wm * 64 + (lid & 15);
    const uint32_t a_cb = (uint32_t)(((lid >> 4) & 1) * 16);
    const int mg = lid >> 3;
    const int b_row0 = wn * 32 + (mg >> 1) * 8 + (lid & 7);
    const uint32_t b_cb = (uint32_t)((mg & 1) * 16);

    const int NIT = Dd / BKC;   // 16
    for (int it = 0; it < NIT; it++) {
        const int s = it & 1;
        if (it + 1 < NIT) {
            prefetch(it + 1, (it + 1) & 1);
            CP_COMMIT();
            CP_WAIT(1);
        } else {
            CP_WAIT(0);
        }
        __syncthreads();

        uint32_t st = sb + s * STG_BYTES;
#pragma unroll
        for (int kt = 0; kt < 4; kt++) {
            uint32_t ah[4][4];
#pragma unroll
            for (int mt = 0; mt < 4; mt++) {
                uint32_t off = (uint32_t)((a_row + mt * 16) * 128) + kt * 32 + a_cb;
                off = SWZ128(off);
                ldsm_x4(ah[mt], st + OFF_A + off);
            }
            uint32_t bh[4][2];
#pragma unroll
            for (int p = 0; p < 2; p++) {
                uint32_t off = (uint32_t)((b_row0 + p * 16) * 128) + kt * 32 + b_cb;
                off = SWZ128(off);
                uint32_t r[4];
                ldsm_x4(r, st + OFF_B + off);
                bh[2 * p][0] = r[0]; bh[2 * p][1] = r[1];
                bh[2 * p + 1][0] = r[2]; bh[2 * p + 1][1] = r[3];
            }
#pragma unroll
            for (int mt = 0; mt < 4; mt++)
#pragma unroll
                for (int nt = 0; nt < 4; nt++)
                    mma_f16(acc[mt][nt], ah[mt], bh[nt]);
        }
        __syncthreads();
    }

    // epilogue
#pragma unroll
    for (int nt = 0; nt < 4; nt++) {
        int c0 = n0 + wn * 32 + nt * 8 + (lid & 3) * 2;
        float b0 = bias[c0], b1 = bias[c0 + 1];
#pragma unroll
        for (int mt = 0; mt < 4; mt++) {
            int r0 = m0 + wm * 64 + mt * 16 + (lid >> 2);
            float v0 = acc[mt][nt][0] + b0, v1 = acc[mt][nt][1] + b1;
            float v2 = acc[mt][nt][2] + b0, v3 = acc[mt][nt][3] + b1;
            if (MODE == 0) {
                *(uint32_t*)&Cq[(size_t)r0 * Dd + c0] = pkh2(v0, v1);
                *(uint32_t*)&Cq[(size_t)(r0 + 8) * Dd + c0] = pkh2(v2, v3);
            } else {
                float2 w0 = {v0, v1}, w1 = {v2, v3};
                *(float2*)&C[(size_t)r0 * Dd + c0] = w0;
                *(float2*)&C[(size_t)(r0 + 8) * Dd + c0] = w1;
            }
        }
    }
}

// ================= Flash attention (all-fp16, causal, max-free softmax) =================
// Q,K,V,P all single fp16 -> 1 MMA per fragment pair. 3-stage KV pipeline,
// mask-free fast path, heavy-first CTA ordering, exp2-domain softmax without max.
constexpr int AT_STG = 16384;                      // K 8KB | V 8KB
constexpr int A_QZ = 3 * AT_STG;                   // Q 16K (reused for out staging)
constexpr int ATT_SMEM = A_QZ + 16384 + 1024;
constexpr float SCL2 = 0.03125f * 1.4426950408889634f;   // (1/32) * log2(e)

template<bool MASK>
__device__ __forceinline__ void attn_tile(
    uint32_t st, int kv0, int r0g, int r1g, int lid,
    int krow, uint32_t kcb, int vrow, uint32_t vcb,
    const uint32_t (&qh)[4][4],
    float (&o)[8][4], float& lsum0, float& lsum1)
{
#pragma unroll
    for (int hf = 0; hf < 2; hf++) {
        // S = Q K^T over 32 keys (single fp16)
        float s[4][4];
#pragma unroll
        for (int nt = 0; nt < 4; nt++)
#pragma unroll
            for (int e = 0; e < 4; e++) s[nt][e] = 0.f;
#pragma unroll
        for (int kd = 0; kd < 4; kd++) {
#pragma unroll
            for (int np = 0; np < 2; np++) {
                uint32_t off = SWZ128((uint32_t)((hf * 32 + np * 16 + krow) * 128) + kd * 32 + kcb);
                uint32_t kh_[4];
                ldsm_x4(kh_, st + off);            // K fp16
                mma_f16(s[2 * np],     qh[kd], kh_);
                mma_f16(s[2 * np + 1], qh[kd], kh_ + 2);
            }
        }

        // P = 2^(scale*S) (no max shift), pack to fp16 A-fragments
        uint32_t pa[2][4];
#pragma unroll
        for (int nt = 0; nt < 4; nt++) {
            float v0, v1, v2, v3;
            if (MASK) {
                int kg = kv0 + hf * 32 + nt * 8 + (lid & 3) * 2;
                v0 = (kg     <= r0g) ? s[nt][0] * SCL2 : -INFINITY;
                v1 = (kg + 1 <= r0g) ? s[nt][1] * SCL2 : -INFINITY;
                v2 = (kg     <= r1g) ? s[nt][2] * SCL2 : -INFINITY;
                v3 = (kg + 1 <= r1g) ? s[nt][3] * SCL2 : -INFINITY;
            } else {
                v0 = s[nt][0] * SCL2; v1 = s[nt][1] * SCL2;
                v2 = s[nt][2] * SCL2; v3 = s[nt][3] * SCL2;
            }
            float p0 = exp2f(v0), p1 = exp2f(v1);
            float p2 = exp2f(v2), p3 = exp2f(v3);
            lsum0 += p0 + p1; lsum1 += p2 + p3;
            int kp = nt >> 1, e = (nt & 1) * 2;
            pa[kp][e]     = pkh2(p0, p1);
            pa[kp][e + 1] = pkh2(p2, p3);
        }

        // O += P V over this 32-key half
#pragma unroll
        for (int kp = 0; kp < 2; kp++) {
#pragma unroll
            for (int np = 0; np < 4; np++) {
                uint32_t off = SWZ128((uint32_t)((hf * 32 + kp * 16 + vrow) * 128) + np * 32 + vcb);
                uint32_t vh_[4];
                ldsm_x4_t(vh_, st + 8192 + off);   // V fp16
                mma_f16(o[2 * np],     pa[kp], vh_);
                mma_f16(o[2 * np + 1], pa[kp], vh_ + 2);
            }
        }
    }
}

__global__ __launch_bounds__(256, 1) void attn_mma()
{
    extern __shared__ char smc[];
    uint32_t sraw = smem_u32(smc);
    uint32_t sb = (sraw + 1023u) & ~1023u;
    char* smb = smc + (sb - sraw);

    const int tid = threadIdx.x, lid = tid & 31, wq = tid >> 5;
    // heavy-first: blockIdx.x = 0 gets the longest (most KV tiles) query block
    const int qi = (gridDim.x - 1) - blockIdx.x;
    const int bh = blockIdx.y;
    const int b = bh >> 4, h = bh & 15;
    const int q0 = qi * 128;
    const size_t base2 = ((size_t)b * Ss * Dd + (size_t)h * DH) * 2;   // bytes

    // Q load: fp16, 128 rows x 128B
#pragma unroll
    for (int i = 0; i < 4; i++) {
        int idx = tid + i * 256;
        int row = idx >> 3; uint32_t colb = (uint32_t)((idx & 7) * 16);
        const char* src = (const char*)g_q16 + base2 + (size_t)(q0 + row) * 2048 + colb;
        cp16(sb + A_QZ + SWZ128((uint32_t)(row * 128) + colb), src);
    }
    CP_COMMIT();

    const char* kvb[2] = {(const char*)g_k16, (const char*)g_v16};
    auto kvload = [&](int kt) {
        uint32_t st = sb + (kt % 3) * AT_STG;
        int kv0 = kt * 64;
#pragma unroll
        for (int i = 0; i < 4; i++) {
            int idx = tid + i * 256;
            int arr = idx >> 9, c = idx & 511;
            int row = c >> 3; uint32_t colb = (uint32_t)((c & 7) * 16);
            cp16(st + arr * 8192 + SWZ128((uint32_t)(row * 128) + colb),
                 kvb[arr] + base2 + (size_t)(kv0 + row) * 2048 + colb);
        }
    };

    const int nkt = 2 * qi + 2;
    kvload(0); CP_COMMIT();
    if (nkt > 1) { kvload(1); CP_COMMIT(); }
    CP_WAIT(2);          // Q group done
    __syncthreads();

    // Q fragments -> registers (4 dim-chunks of 16)
    uint32_t qh[4][4];
    {
        const int a_row = wq * 16 + (lid & 15);
        const uint32_t a_cb = (uint32_t)(((lid >> 4) & 1) * 16);
#pragma unroll
        for (int kd = 0; kd < 4; kd++)
            ldsm_x4(qh[kd], sb + A_QZ + SWZ128((uint32_t)(a_row * 128) + kd * 32 + a_cb));
    }

    float o[8][4];
#pragma unroll
    for (int nt = 0; nt < 8; nt++)
#pragma unroll
        for (int e = 0; e < 4; e++) o[nt][e] = 0.f;
    float lsum0 = 0.f, lsum1 = 0.f;

    const int r0g = q0 + wq * 16 + (lid >> 2);
    const int r1g = r0g + 8;
    const int mg = lid >> 3;
    const int krow = (mg >> 1) * 8 + (lid & 7);
    const uint32_t kcb = (uint32_t)((mg & 1) * 16);
    const int vrow = lid & 15;
    const uint32_t vcb = (uint32_t)((lid >> 4) * 16);

    const int ktfull = 2 * qi;     // tiles [0, ktfull) need no mask
    for (int kt = 0; kt < nkt; kt++) {
        if (kt + 2 < nkt) { kvload(kt + 2); CP_COMMIT(); CP_WAIT(2); }
        else if (kt + 1 < nkt) { CP_WAIT(1); }
        else { CP_WAIT(0); }
        __syncthreads();
        uint32_t st = sb + (kt % 3) * AT_STG;
        if (kt < ktfull)
            attn_tile<false>(st, kt * 64, r0g, r1g, lid, krow, kcb, vrow, vcb,
                             qh, o, lsum0, lsum1);
        else
            attn_tile<true>(st, kt * 64, r0g, r1g, lid, krow, kcb, vrow, vcb,
                            qh, o, lsum0, lsum1);
        __syncthreads();
    }

    // lane reduction of lsum (once per kernel)
    lsum0 += __shfl_xor_sync(0xffffffffu, lsum0, 1);
    lsum0 += __shfl_xor_sync(0xffffffffu, lsum0, 2);
    lsum1 += __shfl_xor_sync(0xffffffffu, lsum1, 1);
    lsum1 += __shfl_xor_sync(0xffffffffu, lsum1, 2);

    // epilogue: normalize, fp16, stage in smem, coalesced store
    float il0 = 1.f / lsum0, il1 = 1.f / lsum1;
    {
        int rs0 = wq * 16 + (lid >> 2);
#pragma unroll
        for (int nt = 0; nt < 8; nt++) {
            uint32_t colb = (uint32_t)(nt * 16 + (lid & 3) * 4);
            *(uint32_t*)(smb + A_QZ + rs0 * 128 + colb)       = pkh2(o[nt][0] * il0, o[nt][1] * il0);
            *(uint32_t*)(smb + A_QZ + (rs0 + 8) * 128 + colb) = pkh2(o[nt][2] * il1, o[nt][3] * il1);
        }
    }
    __syncthreads();
#pragma unroll
    for (int i = 0; i < 4; i++) {
        int idx = tid + i * 256;
        int row = idx >> 3; uint32_t colb = (uint32_t)((idx & 7) * 16);
        uint4 v = *(uint4*)(smb + A_QZ + row * 128 + colb);
        char* dst = (char*)g_a16 + base2 + (size_t)(q0 + row) * 2048 + colb;
        *(uint4*)dst = v;
    }
}

// ---------------- launch ----------------
extern "C" void kernel_launch(void* const* d_in, const int* in_sizes, int n_in,
                              void* d_out, int out_size)
{
    const float* x  = (const float*)d_in[0];
    const float* Wq = (const float*)d_in[1];
    const float* bq = (const float*)d_in[2];
    const float* Wk = (const float*)d_in[3];
    const float* bk = (const float*)d_in[4];
    const float* Wv = (const float*)d_in[5];
    const float* bv = (const float*)d_in[6];
    const float* Wo = (const float*)d_in[7];
    const float* bo = (const float*)d_in[8];
    float* out = (float*)d_out;

    __half *x16, *wt16;
    cudaGetSymbolAddress((void**)&x16,  g_x16);
    cudaGetSymbolAddress((void**)&wt16, g_wt16);

    cudaFuncSetAttribute(gemm_mma<0>,
                         cudaFuncAttributeMaxDynamicSharedMemorySize, GEMM_SMEM);
    cudaFuncSetAttribute(gemm_mma<1>,
                         cudaFuncAttributeMaxDynamicSharedMemorySize, GEMM_SMEM);
    cudaFuncSetAttribute(attn_mma,
                         cudaFuncAttributeMaxDynamicSharedMemorySize, ATT_SMEM);

    transpose_cvt<<<dim3(32, 32, 4), dim3(32, 8)>>>(Wq, Wk, Wv, Wo, wt16);
    cvt_f16<<<(MM * Dd) / 1024, 256>>>(x, x16);

    // Fused QKV projection: one launch, outputs routed to q16/k16/v16
    gemm_mma<0><<<dim3(24, MM / BM), 256, GEMM_SMEM>>>(bq, bk, bv, nullptr);

    attn_mma<<<dim3(Ss / 128, Bb * Hh), 256, ATT_SMEM>>>();

    // Output projection
    gemm_mma<1><<<dim3(8, MM / BM), 256, GEMM_SMEM>>>(bo, nullptr, nullptr, out);
}

// round 13
// speedup vs baseline: 2.7574x; 1.0213x over previous
#include <cuda_runtime.h>
#include <cuda_fp16.h>
#include <math.h>
#include <stdint.h>

// Problem constants
constexpr int Bb = 2, Ss = 2048, Dd = 1024, Hh = 16, DH = 64;
constexpr int MM = Bb * Ss;       // 4096 rows

// ---------------- scratch (no cudaMalloc allowed) ----------------
__device__ __half g_x16[MM * Dd];
__device__ __half g_q16[MM * Dd];
__device__ __half g_k16[MM * Dd];
__device__ __half g_v16[MM * Dd];
__device__ __half g_a16[MM * Dd];
__device__ __half g_wt16[4 * Dd * Dd];    // transposed weights [N,K], Wq|Wk|Wv|Wo

// ================= helpers =================
__device__ __forceinline__ uint32_t smem_u32(const void* p) {
    uint32_t a;
    asm("{ .reg .u64 t; cvta.to.shared.u64 t, %1; cvt.u32.u64 %0, t; }" : "=r"(a) : "l"(p));
    return a;
}
__device__ __forceinline__ void ldsm_x4(uint32_t* r, uint32_t a) {
    asm volatile("ldmatrix.sync.aligned.m8n8.x4.shared.b16 {%0,%1,%2,%3}, [%4];"
                 : "=r"(r[0]), "=r"(r[1]), "=r"(r[2]), "=r"(r[3]) : "r"(a));
}
__device__ __forceinline__ void ldsm_x4_t(uint32_t* r, uint32_t a) {
    asm volatile("ldmatrix.sync.aligned.m8n8.x4.trans.shared.b16 {%0,%1,%2,%3}, [%4];"
                 : "=r"(r[0]), "=r"(r[1]), "=r"(r[2]), "=r"(r[3]) : "r"(a));
}
__device__ __forceinline__ void mma_f16(float* c, const uint32_t* a, const uint32_t* b) {
    asm volatile("mma.sync.aligned.m16n8k16.row.col.f32.f16.f16.f32 "
                 "{%0,%1,%2,%3}, {%4,%5,%6,%7}, {%8,%9}, {%0,%1,%2,%3};"
                 : "+f"(c[0]), "+f"(c[1]), "+f"(c[2]), "+f"(c[3])
                 : "r"(a[0]), "r"(a[1]), "r"(a[2]), "r"(a[3]), "r"(b[0]), "r"(b[1]));
}
__device__ __forceinline__ void cp16(uint32_t dst, const void* src) {
    asm volatile("cp.async.cg.shared.global [%0], [%1], 16;" :: "r"(dst), "l"(src));
}
#define CP_COMMIT() asm volatile("cp.async.commit_group;" ::: "memory")
#define CP_WAIT(n)  asm volatile("cp.async.wait_group %0;" :: "n"(n) : "memory")
#define SWZ128(off) ((off) ^ (((off) >> 3) & 0x70))

__device__ __forceinline__ uint32_t pkh2(float a, float b) {
    __half2 h = __floats2half2_rn(a, b);
    return *(uint32_t*)&h;
}

// ================= prep kernels =================
__global__ __launch_bounds__(256) void cvt_f16(
    const float* __restrict__ in, __half* __restrict__ out)
{
    int i = blockIdx.x * 256 + threadIdx.x;      // float4 index
    float4 v = ((const float4*)in)[i];
    uint2 p;
    p.x = pkh2(v.x, v.y);
    p.y = pkh2(v.z, v.w);
    ((uint2*)out)[i] = p;
}

// transpose W [K,N] -> Wt [N,K] fp16, for 4 weights (blockIdx.z)
__global__ __launch_bounds__(256) void transpose_cvt(
    const float* __restrict__ W0, const float* __restrict__ W1,
    const float* __restrict__ W2, const float* __restrict__ W3,
    __half* __restrict__ out)
{
    __shared__ float sm[32][33];
    const float* W = (blockIdx.z == 0) ? W0 : (blockIdx.z == 1) ? W1 : (blockIdx.z == 2) ? W2 : W3;
    const int tx = threadIdx.x, ty = threadIdx.y;
    const int k0 = blockIdx.y * 32, n0 = blockIdx.x * 32;
#pragma unroll
    for (int i = 0; i < 4; i++)
        sm[ty + 8 * i][tx] = W[(size_t)(k0 + ty + 8 * i) * Dd + n0 + tx];
    __syncthreads();
    size_t zb = (size_t)blockIdx.z * Dd * Dd;
#pragma unroll
    for (int i = 0; i < 4; i++) {
        float v = sm[tx][ty + 8 * i];
        out[zb + (size_t)(n0 + ty + 8 * i) * Dd + k0 + tx] = __float2half_rn(v);
    }
}

// ================= mma.sync GEMM (fp16 single, 1 MMA) =================
constexpr int BM = 128, BN = 128, BKC = 64;
constexpr int STG_BYTES = 32768;               // A 16K | B 16K
constexpr int OFF_A = 0, OFF_B = 16384;
constexpr int GEMM_SMEM = 2 * STG_BYTES + 1024;

template<int MODE>
__global__ __launch_bounds__(256, 2) void gemm_mma(
    const float* __restrict__ bias0, const float* __restrict__ bias1,
    const float* __restrict__ bias2, float* __restrict__ C)
{
    extern __shared__ char smc[];
    uint32_t sraw = smem_u32(smc);
    uint32_t sb = (sraw + 1023u) & ~1023u;

    const int tid = threadIdx.x, lid = tid & 31, wid = tid >> 5;
    const int wm = wid >> 2, wn = wid & 3;
    const int m0 = blockIdx.y * BM;
    const int z = (MODE == 0) ? (blockIdx.x >> 3) : 3;
    const int n0 = (MODE == 0) ? ((blockIdx.x & 7) * BN) : (blockIdx.x * BN);

    const __half* A = (MODE == 0) ? g_x16 : g_a16;
    const __half* B = g_wt16 + (size_t)z * Dd * Dd;
    const float* bias = (MODE == 1) ? bias0 : ((z == 0) ? bias0 : (z == 1) ? bias1 : bias2);
    __half* Cq = nullptr;
    if (MODE == 0) Cq = (z == 0) ? g_q16 : (z == 1) ? g_k16 : g_v16;

    uint32_t dsto[4];
    int rowA[4], rowB[4];
    uint32_t coff[4];
#pragma unroll
    for (int i = 0; i < 4; i++) {
        int idx = tid + i * 256;
        int r = idx >> 3;
        uint32_t off = (uint32_t)(r * 128 + (idx & 7) * 16);
        dsto[i] = SWZ128(off);
        rowA[i] = m0 + r;
        rowB[i] = n0 + r;
        coff[i] = (uint32_t)((idx & 7) * 16);
    }

    auto prefetch = [&](int chunk, int s) {
        uint32_t st = sb + s * STG_BYTES;
        size_t kb = (size_t)chunk * BKC * 2;
#pragma unroll
        for (int i = 0; i < 4; i++) {
            size_t ga = (size_t)rowA[i] * (Dd * 2) + kb + coff[i];
            size_t gb = (size_t)rowB[i] * (Dd * 2) + kb + coff[i];
            cp16(st + OFF_A + dsto[i], (const char*)A + ga);
            cp16(st + OFF_B + dsto[i], (const char*)B + gb);
        }
    };

    float acc[4][4][4];
#pragma unroll
    for (int mt = 0; mt < 4; mt++)
#pragma unroll
        for (int nt = 0; nt < 4; nt++)
#pragma unroll
            for (int e = 0; e < 4; e++) acc[mt][nt][e] = 0.f;

    prefetch(0, 0);
    CP_COMMIT();

    const int a_row = wm * 64 + (lid & 15);
    const uint32_t a_cb = (uint32_t)(((lid >> 4) & 1) * 16);
    const int mg = lid >> 3;
    const int b_row0 = wn * 32 + (mg >> 1) * 8 + (lid & 7);
    const uint32_t b_cb = (uint32_t)((mg & 1) * 16);

    const int NIT = Dd / BKC;   // 16
    for (int it = 0; it < NIT; it++) {
        const int s = it & 1;
        if (it + 1 < NIT) {
            prefetch(it + 1, (it + 1) & 1);
            CP_COMMIT();
            CP_WAIT(1);
        } else {
            CP_WAIT(0);
        }
        __syncthreads();

        uint32_t st = sb + s * STG_BYTES;
#pragma unroll
        for (int kt = 0; kt < 4; kt++) {
            uint32_t ah[4][4];
#pragma unroll
            for (int mt = 0; mt < 4; mt++) {
                uint32_t off = (uint32_t)((a_row + mt * 16) * 128) + kt * 32 + a_cb;
                off = SWZ128(off);
                ldsm_x4(ah[mt], st + OFF_A + off);
            }
            uint32_t bh[4][2];
#pragma unroll
            for (int p = 0; p < 2; p++) {
                uint32_t off = (uint32_t)((b_row0 + p * 16) * 128) + kt * 32 + b_cb;
                off = SWZ128(off);
                uint32_t r[4];
                ldsm_x4(r, st + OFF_B + off);
                bh[2 * p][0] = r[0]; bh[2 * p][1] = r[1];
                bh[2 * p + 1][0] = r[2]; bh[2 * p + 1][1] = r[3];
            }
#pragma unroll
            for (int mt = 0; mt < 4; mt++)
#pragma unroll
                for (int nt = 0; nt < 4; nt++)
                    mma_f16(acc[mt][nt], ah[mt], bh[nt]);
        }
        __syncthreads();
    }

    // epilogue
#pragma unroll
    for (int nt = 0; nt < 4; nt++) {
        int c0 = n0 + wn * 32 + nt * 8 + (lid & 3) * 2;
        float b0 = bias[c0], b1 = bias[c0 + 1];
#pragma unroll
        for (int mt = 0; mt < 4; mt++) {
            int r0 = m0 + wm * 64 + mt * 16 + (lid >> 2);
            float v0 = acc[mt][nt][0] + b0, v1 = acc[mt][nt][1] + b1;
            float v2 = acc[mt][nt][2] + b0, v3 = acc[mt][nt][3] + b1;
            if (MODE == 0) {
                *(uint32_t*)&Cq[(size_t)r0 * Dd + c0] = pkh2(v0, v1);
                *(uint32_t*)&Cq[(size_t)(r0 + 8) * Dd + c0] = pkh2(v2, v3);
            } else {
                float2 w0 = {v0, v1}, w1 = {v2, v3};
                *(float2*)&C[(size_t)r0 * Dd + c0] = w0;
                *(float2*)&C[(size_t)(r0 + 8) * Dd + c0] = w1;
            }
        }
    }
}

// ================= Flash attention (all-fp16, causal, max-free softmax) =================
// BKV=128 tiles, 4-stage pipeline with ONE barrier per tile, lsum via ones-MMA
// (exact fp32 row-sums on the tensor pipe; no shuffle reduction).
constexpr int AT_STG = 32768;                      // K 16KB | V 16KB
constexpr int A_QZ = 4 * AT_STG;                   // Q 16K (reused for out staging)
constexpr int ATT_SMEM = A_QZ + 16384 + 1024;      // ~148KB
constexpr float SCL2 = 0.03125f * 1.4426950408889634f;   // (1/32) * log2(e)

template<bool MASK>
__device__ __forceinline__ void attn_tile(
    uint32_t st, int kv0, int r0g, int r1g, int lid,
    int krow, uint32_t kcb, int vrow, uint32_t vcb,
    const uint32_t (&qh)[4][4],
    float (&o)[8][4], float (&lsc)[4])
{
    const uint32_t ONESB[2] = {0x3C003C00u, 0x3C003C00u};   // fp16 1.0 x4
#pragma unroll
    for (int hf = 0; hf < 4; hf++) {
        // S = Q K^T over 32 keys
        float s[4][4];
#pragma unroll
        for (int nt = 0; nt < 4; nt++)
#pragma unroll
            for (int e = 0; e < 4; e++) s[nt][e] = 0.f;
#pragma unroll
        for (int kd = 0; kd < 4; kd++) {
#pragma unroll
            for (int np = 0; np < 2; np++) {
                uint32_t off = SWZ128((uint32_t)((hf * 32 + np * 16 + krow) * 128) + kd * 32 + kcb);
                uint32_t kh_[4];
                ldsm_x4(kh_, st + off);            // K fp16
                mma_f16(s[2 * np],     qh[kd], kh_);
                mma_f16(s[2 * np + 1], qh[kd], kh_ + 2);
            }
        }

        // P = 2^(scale*S) (no max shift), pack to fp16 A-fragments
        uint32_t pa[2][4];
#pragma unroll
        for (int nt = 0; nt < 4; nt++) {
            float v0, v1, v2, v3;
            if (MASK) {
                int kg = kv0 + hf * 32 + nt * 8 + (lid & 3) * 2;
                v0 = (kg     <= r0g) ? s[nt][0] * SCL2 : -INFINITY;
                v1 = (kg + 1 <= r0g) ? s[nt][1] * SCL2 : -INFINITY;
                v2 = (kg     <= r1g) ? s[nt][2] * SCL2 : -INFINITY;
                v3 = (kg + 1 <= r1g) ? s[nt][3] * SCL2 : -INFINITY;
            } else {
                v0 = s[nt][0] * SCL2; v1 = s[nt][1] * SCL2;
                v2 = s[nt][2] * SCL2; v3 = s[nt][3] * SCL2;
            }
            float p0 = exp2f(v0), p1 = exp2f(v1);
            float p2 = exp2f(v2), p3 = exp2f(v3);
            int kp = nt >> 1, e = (nt & 1) * 2;
            pa[kp][e]     = pkh2(p0, p1);
            pa[kp][e + 1] = pkh2(p2, p3);
        }

        // lsum += P @ ones  (exact fp32 row sums; all 8 columns identical)
        mma_f16(lsc, pa[0], ONESB);
        mma_f16(lsc, pa[1], ONESB);

        // O += P V over this 32-key half
#pragma unroll
        for (int kp = 0; kp < 2; kp++) {
#pragma unroll
            for (int np = 0; np < 4; np++) {
                uint32_t off = SWZ128((uint32_t)((hf * 32 + kp * 16 + vrow) * 128) + np * 32 + vcb);
                uint32_t vh_[4];
                ldsm_x4_t(vh_, st + 16384 + off);  // V fp16
                mma_f16(o[2 * np],     pa[kp], vh_);
                mma_f16(o[2 * np + 1], pa[kp], vh_ + 2);
            }
        }
    }
}

__global__ __launch_bounds__(256, 1) void attn_mma()
{
    extern __shared__ char smc[];
    uint32_t sraw = smem_u32(smc);
    uint32_t sb = (sraw + 1023u) & ~1023u;
    char* smb = smc + (sb - sraw);

    const int tid = threadIdx.x, lid = tid & 31, wq = tid >> 5;
    // heavy-first: blockIdx.x = 0 gets the longest (most KV tiles) query block
    const int qi = (gridDim.x - 1) - blockIdx.x;
    const int bh = blockIdx.y;
    const int b = bh >> 4, h = bh & 15;
    const int q0 = qi * 128;
    const size_t base2 = ((size_t)b * Ss * Dd + (size_t)h * DH) * 2;   // bytes

    // Q load: fp16, 128 rows x 128B
#pragma unroll
    for (int i = 0; i < 4; i++) {
        int idx = tid + i * 256;
        int row = idx >> 3; uint32_t colb = (uint32_t)((idx & 7) * 16);
        const char* src = (const char*)g_q16 + base2 + (size_t)(q0 + row) * 2048 + colb;
        cp16(sb + A_QZ + SWZ128((uint32_t)(row * 128) + colb), src);
    }
    CP_COMMIT();

    const char* kvb[2] = {(const char*)g_k16, (const char*)g_v16};
    auto kvload = [&](int kt) {
        uint32_t st = sb + (kt & 3) * AT_STG;
        int kv0 = kt * 128;
#pragma unroll
        for (int i = 0; i < 8; i++) {
            int idx = tid + i * 256;
            int arr = idx >> 10, c = idx & 1023;
            int row = c >> 3; uint32_t colb = (uint32_t)((c & 7) * 16);
            cp16(st + arr * 16384 + SWZ128((uint32_t)(row * 128) + colb),
                 kvb[arr] + base2 + (size_t)(kv0 + row) * 2048 + colb);
        }
    };

    const int nkt = qi + 1;       // 128-key tiles
    kvload(0); CP_COMMIT();
    if (nkt > 1) {
        kvload(1); CP_COMMIT();
        CP_WAIT(2);               // Q done
    } else {
        CP_WAIT(1);               // Q done
    }
    __syncthreads();

    // Q fragments -> registers (4 dim-chunks of 16)
    uint32_t qh[4][4];
    {
        const int a_row = wq * 16 + (lid & 15);
        const uint32_t a_cb = (uint32_t)(((lid >> 4) & 1) * 16);
#pragma unroll
        for (int kd = 0; kd < 4; kd++)
            ldsm_x4(qh[kd], sb + A_QZ + SWZ128((uint32_t)(a_row * 128) + kd * 32 + a_cb));
    }

    float o[8][4];
#pragma unroll
    for (int nt = 0; nt < 8; nt++)
#pragma unroll
        for (int e = 0; e < 4; e++) o[nt][e] = 0.f;
    float lsc[4] = {0.f, 0.f, 0.f, 0.f};

    const int r0g = q0 + wq * 16 + (lid >> 2);
    const int r1g = r0g + 8;
    const int mg = lid >> 3;
    const int krow = (mg >> 1) * 8 + (lid & 7);
    const uint32_t kcb = (uint32_t)((mg & 1) * 16);
    const int vrow = lid & 15;
    const uint32_t vcb = (uint32_t)((lid >> 4) * 16);

    for (int kt = 0; kt < nkt; kt++) {
        if (kt + 2 < nkt) { kvload(kt + 2); CP_COMMIT(); CP_WAIT(2); }
        else if (kt + 1 < nkt) { CP_WAIT(1); }
        else { CP_WAIT(0); }
        __syncthreads();           // single barrier per tile (4-stage ring)
        uint32_t st = sb + (kt & 3) * AT_STG;
        if (kt < nkt - 1)
            attn_tile<false>(st, kt * 128, r0g, r1g, lid, krow, kcb, vrow, vcb,
                             qh, o, lsc);
        else
            attn_tile<true>(st, kt * 128, r0g, r1g, lid, krow, kcb, vrow, vcb,
                            qh, o, lsc);
    }

    // row sums come straight from the ones-MMA accumulator (exact, no shuffles)
    float il0 = 1.f / lsc[0], il1 = 1.f / lsc[2];

    // epilogue: normalize, fp16, stage in smem, coalesced store
    {
        int rs0 = wq * 16 + (lid >> 2);
#pragma unroll
        for (int nt = 0; nt < 8; nt++) {
            uint32_t colb = (uint32_t)(nt * 16 + (lid & 3) * 4);
            *(uint32_t*)(smb + A_QZ + rs0 * 128 + colb)       = pkh2(o[nt][0] * il0, o[nt][1] * il0);
            *(uint32_t*)(smb + A_QZ + (rs0 + 8) * 128 + colb) = pkh2(o[nt][2] * il1, o[nt][3] * il1);
        }
    }
    __syncthreads();
#pragma unroll
    for (int i = 0; i < 4; i++) {
        int idx = tid + i * 256;
        int row = idx >> 3; uint32_t colb = (uint32_t)((idx & 7) * 16);
        uint4 v = *(uint4*)(smb + A_QZ + row * 128 + colb);
        char* dst = (char*)g_a16 + base2 + (size_t)(q0 + row) * 2048 + colb;
        *(uint4*)dst = v;
    }
}

// ---------------- launch ----------------
extern "C" void kernel_launch(void* const* d_in, const int* in_sizes, int n_in,
                              void* d_out, int out_size)
{
    const float* x  = (const float*)d_in[0];
    const float* Wq = (const float*)d_in[1];
    const float* bq = (const float*)d_in[2];
    const float* Wk = (const float*)d_in[3];
    const float* bk = (const float*)d_in[4];
    const float* Wv = (const float*)d_in[5];
    const float* bv = (const float*)d_in[6];
    const float* Wo = (const float*)d_in[7];
    const float* bo = (const float*)d_in[8];
    float* out = (float*)d_out;

    __half *x16, *wt16;
    cudaGetSymbolAddress((void**)&x16,  g_x16);
    cudaGetSymbolAddress((void**)&wt16, g_wt16);

    cudaFuncSetAttribute(gemm_mma<0>,
                         cudaFuncAttributeMaxDynamicSharedMemorySize, GEMM_SMEM);
    cudaFuncSetAttribute(gemm_mma<1>,
                         cudaFuncAttributeMaxDynamicSharedMemorySize, GEMM_SMEM);
    cudaFuncSetAttribute(attn_mma,
                         cudaFuncAttributeMaxDynamicSharedMemorySize, ATT_SMEM);

    transpose_cvt<<<dim3(32, 32, 4), dim3(32, 8)>>>(Wq, Wk, Wv, Wo, wt16);
    cvt_f16<<<(MM * Dd) / 1024, 256>>>(x, x16);

    // Fused QKV projection: one launch, outputs routed to q16/k16/v16
    gemm_mma<0><<<dim3(24, MM / BM), 256, GEMM_SMEM>>>(bq, bk, bv, nullptr);

    attn_mma<<<dim3(Ss / 128, Bb * Hh), 256, ATT_SMEM>>>();

    // Output projection
    gemm_mma<1><<<dim3(8, MM / BM), 256, GEMM_SMEM>>>(bo, nullptr, nullptr, out);
}

// round 15
// speedup vs baseline: 2.9252x; 1.0609x over previous
#include <cuda_runtime.h>
#include <cuda_fp16.h>
#include <math.h>
#include <stdint.h>

// Problem constants
constexpr int Bb = 2, Ss = 2048, Dd = 1024, Hh = 16, DH = 64;
constexpr int MM = Bb * Ss;       // 4096 rows

// ---------------- scratch (no cudaMalloc allowed) ----------------
__device__ __half g_x16[MM * Dd];
__device__ __half g_q16[MM * Dd];     // pre-scaled by SCL2 (log2-domain QK)
__device__ __half g_k16[MM * Dd];
__device__ __half g_v16[MM * Dd];
__device__ __half g_a16[MM * Dd];
__device__ __half g_wt16[4 * Dd * Dd];    // transposed weights [N,K], Wq|Wk|Wv|Wo

constexpr float SCL2 = 0.03125f * 1.4426950408889634f;   // (1/32) * log2(e)

// ================= helpers =================
__device__ __forceinline__ uint32_t smem_u32(const void* p) {
    uint32_t a;
    asm("{ .reg .u64 t; cvta.to.shared.u64 t, %1; cvt.u32.u64 %0, t; }" : "=r"(a) : "l"(p));
    return a;
}
__device__ __forceinline__ void ldsm_x4(uint32_t* r, uint32_t a) {
    asm volatile("ldmatrix.sync.aligned.m8n8.x4.shared.b16 {%0,%1,%2,%3}, [%4];"
                 : "=r"(r[0]), "=r"(r[1]), "=r"(r[2]), "=r"(r[3]) : "r"(a));
}
__device__ __forceinline__ void ldsm_x4_t(uint32_t* r, uint32_t a) {
    asm volatile("ldmatrix.sync.aligned.m8n8.x4.trans.shared.b16 {%0,%1,%2,%3}, [%4];"
                 : "=r"(r[0]), "=r"(r[1]), "=r"(r[2]), "=r"(r[3]) : "r"(a));
}
__device__ __forceinline__ void mma_f16(float* c, const uint32_t* a, const uint32_t* b) {
    asm volatile("mma.sync.aligned.m16n8k16.row.col.f32.f16.f16.f32 "
                 "{%0,%1,%2,%3}, {%4,%5,%6,%7}, {%8,%9}, {%0,%1,%2,%3};"
                 : "+f"(c[0]), "+f"(c[1]), "+f"(c[2]), "+f"(c[3])
                 : "r"(a[0]), "r"(a[1]), "r"(a[2]), "r"(a[3]), "r"(b[0]), "r"(b[1]));
}
__device__ __forceinline__ void cp16(uint32_t dst, const void* src) {
    asm volatile("cp.async.cg.shared.global [%0], [%1], 16;" :: "r"(dst), "l"(src));
}
#define CP_COMMIT() asm volatile("cp.async.commit_group;" ::: "memory")
#define CP_WAIT(n)  asm volatile("cp.async.wait_group %0;" :: "n"(n) : "memory")
#define SWZ128(off) ((off) ^ (((off) >> 3) & 0x70))

__device__ __forceinline__ uint32_t pkh2(float a, float b) {
    __half2 h = __floats2half2_rn(a, b);
    return *(uint32_t*)&h;
}
__device__ __forceinline__ uint32_t ex2_h2(uint32_t v) {
    uint32_t r;
    asm volatile("ex2.approx.f16x2 %0, %1;" : "=r"(r) : "r"(v));
    return r;
}

// ================= prep kernel (fused) =================
// z in 0..3 -> transpose W_z; z in 4..7 -> x fp32->fp16 (4 slices x 1024 CTAs)
__global__ __launch_bounds__(256) void prep_all(
    const float* __restrict__ x,
    const float* __restrict__ W0, const float* __restrict__ W1,
    const float* __restrict__ W2, const float* __restrict__ W3,
    __half* __restrict__ x16, __half* __restrict__ wt16)
{
    if (blockIdx.z >= 4) {
        // x fp32 -> fp16: 4 slices x (32x32 CTAs) x 256 thr x float4 = 4M floats
        int i = (((int)blockIdx.z - 4) * 1024 + (int)blockIdx.y * 32 + (int)blockIdx.x) * 256
                + (int)threadIdx.x;
        float4 v = ((const float4*)x)[i];
        uint2 p;
        p.x = pkh2(v.x, v.y);
        p.y = pkh2(v.z, v.w);
        ((uint2*)x16)[i] = p;
        return;
    }
    __shared__ float sm[32][33];
    const float* W = (blockIdx.z == 0) ? W0 : (blockIdx.z == 1) ? W1 : (blockIdx.z == 2) ? W2 : W3;
    const int tx = threadIdx.x & 31, ty = threadIdx.x >> 5;
    const int k0 = blockIdx.y * 32, n0 = blockIdx.x * 32;
#pragma unroll
    for (int i = 0; i < 4; i++)
        sm[ty + 8 * i][tx] = W[(size_t)(k0 + ty + 8 * i) * Dd + n0 + tx];
    __syncthreads();
    size_t zb = (size_t)blockIdx.z * Dd * Dd;
#pragma unroll
    for (int i = 0; i < 4; i++) {
        float v = sm[tx][ty + 8 * i];
        wt16[zb + (size_t)(n0 + ty + 8 * i) * Dd + k0 + tx] = __float2half_rn(v);
    }
}

// ================= mma.sync GEMM (fp16 single, 1 MMA) =================
// MODE 0: QKV (z==0 output pre-scaled by SCL2). MODE 1: O projection, fp32 out.
constexpr int BM = 128, BN = 128, BKC = 64;
constexpr int STG_BYTES = 32768;               // A 16K | B 16K
constexpr int OFF_A = 0, OFF_B = 16384;
constexpr int GEMM_SMEM = 2 * STG_BYTES + 1024;

template<int MODE>
__global__ __launch_bounds__(256, 2) void gemm_mma(
    const float* __restrict__ bias0, const float* __restrict__ bias1,
    const float* __restrict__ bias2, float* __restrict__ C)
{
    extern __shared__ char smc[];
    uint32_t sraw = smem_u32(smc);
    uint32_t sb = (sraw + 1023u) & ~1023u;

    const int tid = threadIdx.x, lid = tid & 31, wid = tid >> 5;
    const int wm = wid >> 2, wn = wid & 3;
    const int m0 = blockIdx.y * BM;
    const int z = (MODE == 0) ? (blockIdx.x >> 3) : 3;
    const int n0 = (MODE == 0) ? ((blockIdx.x & 7) * BN) : (blockIdx.x * BN);

    const __half* A = (MODE == 0) ? g_x16 : g_a16;
    const __half* B = g_wt16 + (size_t)z * Dd * Dd;
    const float* bias = (MODE == 1) ? bias0 : ((z == 0) ? bias0 : (z == 1) ? bias1 : bias2);
    __half* Cq = nullptr;
    if (MODE == 0) Cq = (z == 0) ? g_q16 : (z == 1) ? g_k16 : g_v16;
    const float oscl = (MODE == 0 && z == 0) ? SCL2 : 1.0f;

    uint32_t dsto[4];
    int rowA[4], rowB[4];
    uint32_t coff[4];
#pragma unroll
    for (int i = 0; i < 4; i++) {
        int idx = tid + i * 256;
        int r = idx >> 3;
        uint32_t off = (uint32_t)(r * 128 + (idx & 7) * 16);
        dsto[i] = SWZ128(off);
        rowA[i] = m0 + r;
        rowB[i] = n0 + r;
        coff[i] = (uint32_t)((idx & 7) * 16);
    }

    auto prefetch = [&](int chunk, int s) {
        uint32_t st = sb + s * STG_BYTES;
        size_t kb = (size_t)chunk * BKC * 2;
#pragma unroll
        for (int i = 0; i < 4; i++) {
            size_t ga = (size_t)rowA[i] * (Dd * 2) + kb + coff[i];
            size_t gb = (size_t)rowB[i] * (Dd * 2) + kb + coff[i];
            cp16(st + OFF_A + dsto[i], (const char*)A + ga);
            cp16(st + OFF_B + dsto[i], (const char*)B + gb);
        }
    };

    float acc[4][4][4];
#pragma unroll
    for (int mt = 0; mt < 4; mt++)
#pragma unroll
        for (int nt = 0; nt < 4; nt++)
#pragma unroll
            for (int e = 0; e < 4; e++) acc[mt][nt][e] = 0.f;

    prefetch(0, 0);
    CP_COMMIT();

    const int a_row = wm * 64 + (lid & 15);
    const uint32_t a_cb = (uint32_t)(((lid >> 4) & 1) * 16);
    const int mg = lid >> 3;
    const int b_row0 = wn * 32 + (mg >> 1) * 8 + (lid & 7);
    const uint32_t b_cb = (uint32_t)((mg & 1) * 16);

    const int NIT = Dd / BKC;   // 16
    for (int it = 0; it < NIT; it++) {
        const int s = it & 1;
        if (it + 1 < NIT) {
            prefetch(it + 1, (it + 1) & 1);
            CP_COMMIT();
            CP_WAIT(1);
        } else {
            CP_WAIT(0);
        }
        __syncthreads();

        uint32_t st = sb + s * STG_BYTES;
#pragma unroll
        for (int kt = 0; kt < 4; kt++) {
            uint32_t ah[4][4];
#pragma unroll
            for (int mt = 0; mt < 4; mt++) {
                uint32_t off = (uint32_t)((a_row + mt * 16) * 128) + kt * 32 + a_cb;
                off = SWZ128(off);
                ldsm_x4(ah[mt], st + OFF_A + off);
            }
            uint32_t bh[4][2];
#pragma unroll
            for (int p = 0; p < 2; p++) {
                uint32_t off = (uint32_t)((b_row0 + p * 16) * 128) + kt * 32 + b_cb;
                off = SWZ128(off);
                uint32_t r[4];
                ldsm_x4(r, st + OFF_B + off);
                bh[2 * p][0] = r[0]; bh[2 * p][1] = r[1];
                bh[2 * p + 1][0] = r[2]; bh[2 * p + 1][1] = r[3];
            }
#pragma unroll
            for (int mt = 0; mt < 4; mt++)
#pragma unroll
                for (int nt = 0; nt < 4; nt++)
                    mma_f16(acc[mt][nt], ah[mt], bh[nt]);
        }
        __syncthreads();
    }

    // epilogue
#pragma unroll
    for (int nt = 0; nt < 4; nt++) {
        int c0 = n0 + wn * 32 + nt * 8 + (lid & 3) * 2;
        float b0 = bias[c0], b1 = bias[c0 + 1];
#pragma unroll
        for (int mt = 0; mt < 4; mt++) {
            int r0 = m0 + wm * 64 + mt * 16 + (lid >> 2);
            float v0 = (acc[mt][nt][0] + b0) * oscl, v1 = (acc[mt][nt][1] + b1) * oscl;
            float v2 = (acc[mt][nt][2] + b0) * oscl, v3 = (acc[mt][nt][3] + b1) * oscl;
            if (MODE == 0) {
                *(uint32_t*)&Cq[(size_t)r0 * Dd + c0] = pkh2(v0, v1);
                *(uint32_t*)&Cq[(size_t)(r0 + 8) * Dd + c0] = pkh2(v2, v3);
            } else {
                float2 w0 = {v0, v1}, w1 = {v2, v3};
                *(float2*)&C[(size_t)r0 * Dd + c0] = w0;
                *(float2*)&C[(size_t)(r0 + 8) * Dd + c0] = w1;
            }
        }
    }
}

// ================= Flash attention (all-fp16, causal, max-free softmax) =================
// Q pre-scaled (QK^T directly in log2 domain); P = ex2.approx.f16x2 of the
// half2-packed scores (MUFU count halved). BKV=128 tiles, 4-stage pipeline,
// one barrier/tile, lsum via ones-MMA.
constexpr int AT_STG = 32768;                      // K 16KB | V 16KB
constexpr int A_QZ = 4 * AT_STG;                   // Q 16K (reused for out staging)
constexpr int ATT_SMEM = A_QZ + 16384 + 1024;      // ~148KB

template<bool MASK>
__device__ __forceinline__ void attn_tile(
    uint32_t st, int kv0, int r0g, int r1g, int lid,
    int krow, uint32_t kcb, int vrow, uint32_t vcb,
    const uint32_t (&qh)[4][4],
    float (&o)[8][4], float (&lsc)[4])
{
    const uint32_t ONESB[2] = {0x3C003C00u, 0x3C003C00u};   // fp16 1.0 x4
#pragma unroll
    for (int hf = 0; hf < 4; hf++) {
        // S = Q K^T over 32 keys (already in log2 domain via pre-scaled Q)
        float s[4][4];
#pragma unroll
        for (int nt = 0; nt < 4; nt++)
#pragma unroll
            for (int e = 0; e < 4; e++) s[nt][e] = 0.f;
#pragma unroll
        for (int kd = 0; kd < 4; kd++) {
#pragma unroll
            for (int np = 0; np < 2; np++) {
                uint32_t off = SWZ128((uint32_t)((hf * 32 + np * 16 + krow) * 128) + kd * 32 + kcb);
                uint32_t kh_[4];
                ldsm_x4(kh_, st + off);            // K fp16
                mma_f16(s[2 * np],     qh[kd], kh_);
                mma_f16(s[2 * np + 1], qh[kd], kh_ + 2);
            }
        }

        // P = 2^s via half2 EX2 (pack first, halves MUFU count)
        uint32_t pa[2][4];
#pragma unroll
        for (int nt = 0; nt < 4; nt++) {
            float v0 = s[nt][0], v1 = s[nt][1], v2 = s[nt][2], v3 = s[nt][3];
            if (MASK) {
                int kg = kv0 + hf * 32 + nt * 8 + (lid & 3) * 2;
                v0 = (kg     <= r0g) ? v0 : -INFINITY;
                v1 = (kg + 1 <= r0g) ? v1 : -INFINITY;
                v2 = (kg     <= r1g) ? v2 : -INFINITY;
                v3 = (kg + 1 <= r1g) ? v3 : -INFINITY;
            }
            int kp = nt >> 1, e = (nt & 1) * 2;
            pa[kp][e]     = ex2_h2(pkh2(v0, v1));
            pa[kp][e + 1] = ex2_h2(pkh2(v2, v3));
        }

        // lsum += P @ ones  (exact fp32 row sums)
        mma_f16(lsc, pa[0], ONESB);
        mma_f16(lsc, pa[1], ONESB);

        // O += P V over this 32-key half
#pragma unroll
        for (int kp = 0; kp < 2; kp++) {
#pragma unroll
            for (int np = 0; np < 4; np++) {
                uint32_t off = SWZ128((uint32_t)((hf * 32 + kp * 16 + vrow) * 128) + np * 32 + vcb);
                uint32_t vh_[4];
                ldsm_x4_t(vh_, st + 16384 + off);  // V fp16
                mma_f16(o[2 * np],     pa[kp], vh_);
                mma_f16(o[2 * np + 1], pa[kp], vh_ + 2);
            }
        }
    }
}

__global__ __launch_bounds__(256, 1) void attn_mma()
{
    extern __shared__ char smc[];
    uint32_t sraw = smem_u32(smc);
    uint32_t sb = (sraw + 1023u) & ~1023u;
    char* smb = smc + (sb - sraw);

    const int tid = threadIdx.x, lid = tid & 31, wq = tid >> 5;
    // heavy-first: blockIdx.x = 0 gets the longest (most KV tiles) query block
    const int qi = (gridDim.x - 1) - blockIdx.x;
    const int bh = blockIdx.y;
    const int b = bh >> 4, h = bh & 15;
    const int q0 = qi * 128;
    const size_t base2 = ((size_t)b * Ss * Dd + (size_t)h * DH) * 2;   // bytes

    // Q load: fp16, 128 rows x 128B
#pragma unroll
    for (int i = 0; i < 4; i++) {
        int idx = tid + i * 256;
        int row = idx >> 3; uint32_t colb = (uint32_t)((idx & 7) * 16);
        const char* src = (const char*)g_q16 + base2 + (size_t)(q0 + row) * 2048 + colb;
        cp16(sb + A_QZ + SWZ128((uint32_t)(row * 128) + colb), src);
    }
    CP_COMMIT();

    const char* kvb[2] = {(const char*)g_k16, (const char*)g_v16};
    auto kvload = [&](int kt) {
        uint32_t st = sb + (kt & 3) * AT_STG;
        int kv0 = kt * 128;
#pragma unroll
        for (int i = 0; i < 8; i++) {
            int idx = tid + i * 256;
            int arr = idx >> 10, c = idx & 1023;
            int row = c >> 3; uint32_t colb = (uint32_t)((c & 7) * 16);
            cp16(st + arr * 16384 + SWZ128((uint32_t)(row * 128) + colb),
                 kvb[arr] + base2 + (size_t)(kv0 + row) * 2048 + colb);
        }
    };

    const int nkt = qi + 1;       // 128-key tiles
    kvload(0); CP_COMMIT();
    if (nkt > 1) {
        kvload(1); CP_COMMIT();
        CP_WAIT(2);               // Q done
    } else {
        CP_WAIT(1);               // Q done
    }
    __syncthreads();

    // Q fragments -> registers (4 dim-chunks of 16)
    uint32_t qh[4][4];
    {
        const int a_row = wq * 16 + (lid & 15);
        const uint32_t a_cb = (uint32_t)(((lid >> 4) & 1) * 16);
#pragma unroll
        for (int kd = 0; kd < 4; kd++)
            ldsm_x4(qh[kd], sb + A_QZ + SWZ128((uint32_t)(a_row * 128) + kd * 32 + a_cb));
    }

    float o[8][4];
#pragma unroll
    for (int nt = 0; nt < 8; nt++)
#pragma unroll
        for (int e = 0; e < 4; e++) o[nt][e] = 0.f;
    float lsc[4] = {0.f, 0.f, 0.f, 0.f};

    const int r0g = q0 + wq * 16 + (lid >> 2);
    const int r1g = r0g + 8;
    const int mg = lid >> 3;
    const int krow = (mg >> 1) * 8 + (lid & 7);
    const uint32_t kcb = (uint32_t)((mg & 1) * 16);
    const int vrow = lid & 15;
    const uint32_t vcb = (uint32_t)((lid >> 4) * 16);

    for (int kt = 0; kt < nkt; kt++) {
        if (kt + 2 < nkt) { kvload(kt + 2); CP_COMMIT(); CP_WAIT(2); }
        else if (kt + 1 < nkt) { CP_WAIT(1); }
        else { CP_WAIT(0); }
        __syncthreads();           // single barrier per tile (4-stage ring)
        uint32_t st = sb + (kt & 3) * AT_STG;
        if (kt < nkt - 1)
            attn_tile<false>(st, kt * 128, r0g, r1g, lid, krow, kcb, vrow, vcb,
                             qh, o, lsc);
        else
            attn_tile<true>(st, kt * 128, r0g, r1g, lid, krow, kcb, vrow, vcb,
                            qh, o, lsc);
    }

    // row sums come straight from the ones-MMA accumulator
    float il0 = 1.f / lsc[0], il1 = 1.f / lsc[2];

    // epilogue: normalize, fp16, stage in smem, coalesced store
    {
        int rs0 = wq * 16 + (lid >> 2);
#pragma unroll
        for (int nt = 0; nt < 8; nt++) {
            uint32_t colb = (uint32_t)(nt * 16 + (lid & 3) * 4);
            *(uint32_t*)(smb + A_QZ + rs0 * 128 + colb)       = pkh2(o[nt][0] * il0, o[nt][1] * il0);
            *(uint32_t*)(smb + A_QZ + (rs0 + 8) * 128 + colb) = pkh2(o[nt][2] * il1, o[nt][3] * il1);
        }
    }
    __syncthreads();
#pragma unroll
    for (int i = 0; i < 4; i++) {
        int idx = tid + i * 256;
        int row = idx >> 3; uint32_t colb = (uint32_t)((idx & 7) * 16);
        uint4 v = *(uint4*)(smb + A_QZ + row * 128 + colb);
        char* dst = (char*)g_a16 + base2 + (size_t)(q0 + row) * 2048 + colb;
        *(uint4*)dst = v;
    }
}

// ---------------- launch ----------------
extern "C" void kernel_launch(void* const* d_in, const int* in_sizes, int n_in,
                              void* d_out, int out_size)
{
    const float* x  = (const float*)d_in[0];
    const float* Wq = (const float*)d_in[1];
    const float* bq = (const float*)d_in[2];
    const float* Wk = (const float*)d_in[3];
    const float* bk = (const float*)d_in[4];
    const float* Wv = (const float*)d_in[5];
    const float* bv = (const float*)d_in[6];
    const float* Wo = (const float*)d_in[7];
    const float* bo = (const float*)d_in[8];
    float* out = (float*)d_out;

    __half *x16, *wt16;
    cudaGetSymbolAddress((void**)&x16,  g_x16);
    cudaGetSymbolAddress((void**)&wt16, g_wt16);

    cudaFuncSetAttribute(gemm_mma<0>,
                         cudaFuncAttributeMaxDynamicSharedMemorySize, GEMM_SMEM);
    cudaFuncSetAttribute(gemm_mma<1>,
                         cudaFuncAttributeMaxDynamicSharedMemorySize, GEMM_SMEM);
    cudaFuncSetAttribute(attn_mma,
                         cudaFuncAttributeMaxDynamicSharedMemorySize, ATT_SMEM);

    // fused prep: z 0..3 = transpose Wq/Wk/Wv/Wo, z 4..7 = x fp32->fp16 slices
    prep_all<<<dim3(32, 32, 8), 256>>>(x, Wq, Wk, Wv, Wo, x16, wt16);

    // Fused QKV projection: one launch, outputs routed to q16(scaled)/k16/v16
    gemm_mma<0><<<dim3(24, MM / BM), 256, GEMM_SMEM>>>(bq, bk, bv, nullptr);

    attn_mma<<<dim3(Ss / 128, Bb * Hh), 256, ATT_SMEM>>>();

    // Output projection
    gemm_mma<1><<<dim3(8, MM / BM), 256, GEMM_SMEM>>>(bo, nullptr, nullptr, out);
}

// round 16
// speedup vs baseline: 3.1440x; 1.0748x over previous
#include <cuda_runtime.h>
#include <cuda_fp16.h>
#include <math.h>
#include <stdint.h>

// Problem constants
constexpr int Bb = 2, Ss = 2048, Dd = 1024, Hh = 16, DH = 64;
constexpr int MM = Bb * Ss;       // 4096 rows

// ---------------- scratch (no cudaMalloc allowed) ----------------
__device__ __half g_x16[MM * Dd];
__device__ __half g_q16[MM * Dd];     // pre-scaled by SCL2 (log2-domain QK)
__device__ __half g_k16[MM * Dd];
__device__ __half g_v16[MM * Dd];
__device__ __half g_a16[MM * Dd];
__device__ __half g_wt16[4 * Dd * Dd];    // transposed weights [N,K], Wq|Wk|Wv|Wo

constexpr float SCL2 = 0.03125f * 1.4426950408889634f;   // (1/32) * log2(e)

// ================= helpers =================
__device__ __forceinline__ uint32_t smem_u32(const void* p) {
    uint32_t a;
    asm("{ .reg .u64 t; cvta.to.shared.u64 t, %1; cvt.u32.u64 %0, t; }" : "=r"(a) : "l"(p));
    return a;
}
__device__ __forceinline__ void ldsm_x4(uint32_t* r, uint32_t a) {
    asm volatile("ldmatrix.sync.aligned.m8n8.x4.shared.b16 {%0,%1,%2,%3}, [%4];"
                 : "=r"(r[0]), "=r"(r[1]), "=r"(r[2]), "=r"(r[3]) : "r"(a));
}
__device__ __forceinline__ void ldsm_x4_t(uint32_t* r, uint32_t a) {
    asm volatile("ldmatrix.sync.aligned.m8n8.x4.trans.shared.b16 {%0,%1,%2,%3}, [%4];"
                 : "=r"(r[0]), "=r"(r[1]), "=r"(r[2]), "=r"(r[3]) : "r"(a));
}
__device__ __forceinline__ void mma_f16(float* c, const uint32_t* a, const uint32_t* b) {
    asm volatile("mma.sync.aligned.m16n8k16.row.col.f32.f16.f16.f32 "
                 "{%0,%1,%2,%3}, {%4,%5,%6,%7}, {%8,%9}, {%0,%1,%2,%3};"
                 : "+f"(c[0]), "+f"(c[1]), "+f"(c[2]), "+f"(c[3])
                 : "r"(a[0]), "r"(a[1]), "r"(a[2]), "r"(a[3]), "r"(b[0]), "r"(b[1]));
}
__device__ __forceinline__ void cp16(uint32_t dst, const void* src) {
    asm volatile("cp.async.cg.shared.global [%0], [%1], 16;" :: "r"(dst), "l"(src));
}
#define CP_COMMIT() asm volatile("cp.async.commit_group;" ::: "memory")
#define CP_WAIT(n)  asm volatile("cp.async.wait_group %0;" :: "n"(n) : "memory")
#define SWZ128(off) ((off) ^ (((off) >> 3) & 0x70))

__device__ __forceinline__ uint32_t pkh2(float a, float b) {
    __half2 h = __floats2half2_rn(a, b);
    return *(uint32_t*)&h;
}
__device__ __forceinline__ uint32_t ex2_h2(uint32_t v) {
    uint32_t r;
    asm volatile("ex2.approx.f16x2 %0, %1;" : "=r"(r) : "r"(v));
    return r;
}

// ================= prep kernel (fused) =================
// z in 0..3 -> transpose W_z; z in 4..7 -> x fp32->fp16 (4 slices x 1024 CTAs)
__global__ __launch_bounds__(256) void prep_all(
    const float* __restrict__ x,
    const float* __restrict__ W0, const float* __restrict__ W1,
    const float* __restrict__ W2, const float* __restrict__ W3,
    __half* __restrict__ x16, __half* __restrict__ wt16)
{
    if (blockIdx.z >= 4) {
        int i = (((int)blockIdx.z - 4) * 1024 + (int)blockIdx.y * 32 + (int)blockIdx.x) * 256
                + (int)threadIdx.x;
        float4 v = ((const float4*)x)[i];
        uint2 p;
        p.x = pkh2(v.x, v.y);
        p.y = pkh2(v.z, v.w);
        ((uint2*)x16)[i] = p;
        return;
    }
    __shared__ float sm[32][33];
    const float* W = (blockIdx.z == 0) ? W0 : (blockIdx.z == 1) ? W1 : (blockIdx.z == 2) ? W2 : W3;
    const int tx = threadIdx.x & 31, ty = threadIdx.x >> 5;
    const int k0 = blockIdx.y * 32, n0 = blockIdx.x * 32;
#pragma unroll
    for (int i = 0; i < 4; i++)
        sm[ty + 8 * i][tx] = W[(size_t)(k0 + ty + 8 * i) * Dd + n0 + tx];
    __syncthreads();
    size_t zb = (size_t)blockIdx.z * Dd * Dd;
#pragma unroll
    for (int i = 0; i < 4; i++) {
        float v = sm[tx][ty + 8 * i];
        wt16[zb + (size_t)(n0 + ty + 8 * i) * Dd + k0 + tx] = __float2half_rn(v);
    }
}

// ================= mma.sync GEMM (fp16 single, 1 MMA) =================
// MODE 0: QKV (z==0 output pre-scaled by SCL2). MODE 1: O projection, fp32 out.
constexpr int BM = 128, BN = 128, BKC = 64;
constexpr int STG_BYTES = 32768;               // A 16K | B 16K
constexpr int OFF_A = 0, OFF_B = 16384;
constexpr int GEMM_SMEM = 2 * STG_BYTES + 1024;

template<int MODE>
__global__ __launch_bounds__(256, 2) void gemm_mma(
    const float* __restrict__ bias0, const float* __restrict__ bias1,
    const float* __restrict__ bias2, float* __restrict__ C)
{
    extern __shared__ char smc[];
    uint32_t sraw = smem_u32(smc);
    uint32_t sb = (sraw + 1023u) & ~1023u;

    const int tid = threadIdx.x, lid = tid & 31, wid = tid >> 5;
    const int wm = wid >> 2, wn = wid & 3;
    const int m0 = blockIdx.y * BM;
    const int z = (MODE == 0) ? (blockIdx.x >> 3) : 3;
    const int n0 = (MODE == 0) ? ((blockIdx.x & 7) * BN) : (blockIdx.x * BN);

    const __half* A = (MODE == 0) ? g_x16 : g_a16;
    const __half* B = g_wt16 + (size_t)z * Dd * Dd;
    const float* bias = (MODE == 1) ? bias0 : ((z == 0) ? bias0 : (z == 1) ? bias1 : bias2);
    __half* Cq = nullptr;
    if (MODE == 0) Cq = (z == 0) ? g_q16 : (z == 1) ? g_k16 : g_v16;
    const float oscl = (MODE == 0 && z == 0) ? SCL2 : 1.0f;

    uint32_t dsto[4];
    int rowA[4], rowB[4];
    uint32_t coff[4];
#pragma unroll
    for (int i = 0; i < 4; i++) {
        int idx = tid + i * 256;
        int r = idx >> 3;
        uint32_t off = (uint32_t)(r * 128 + (idx & 7) * 16);
        dsto[i] = SWZ128(off);
        rowA[i] = m0 + r;
        rowB[i] = n0 + r;
        coff[i] = (uint32_t)((idx & 7) * 16);
    }

    auto prefetch = [&](int chunk, int s) {
        uint32_t st = sb + s * STG_BYTES;
        size_t kb = (size_t)chunk * BKC * 2;
#pragma unroll
        for (int i = 0; i < 4; i++) {
            size_t ga = (size_t)rowA[i] * (Dd * 2) + kb + coff[i];
            size_t gb = (size_t)rowB[i] * (Dd * 2) + kb + coff[i];
            cp16(st + OFF_A + dsto[i], (const char*)A + ga);
            cp16(st + OFF_B + dsto[i], (const char*)B + gb);
        }
    };

    float acc[4][4][4];
#pragma unroll
    for (int mt = 0; mt < 4; mt++)
#pragma unroll
        for (int nt = 0; nt < 4; nt++)
#pragma unroll
            for (int e = 0; e < 4; e++) acc[mt][nt][e] = 0.f;

    prefetch(0, 0);
    CP_COMMIT();

    const int a_row = wm * 64 + (lid & 15);
    const uint32_t a_cb = (uint32_t)(((lid >> 4) & 1) * 16);
    const int mg = lid >> 3;
    const int b_row0 = wn * 32 + (mg >> 1) * 8 + (lid & 7);
    const uint32_t b_cb = (uint32_t)((mg & 1) * 16);

    const int NIT = Dd / BKC;   // 16
    for (int it = 0; it < NIT; it++) {
        const int s = it & 1;
        if (it + 1 < NIT) {
            prefetch(it + 1, (it + 1) & 1);
            CP_COMMIT();
            CP_WAIT(1);
        } else {
            CP_WAIT(0);
        }
        __syncthreads();

        uint32_t st = sb + s * STG_BYTES;
#pragma unroll
        for (int kt = 0; kt < 4; kt++) {
            uint32_t ah[4][4];
#pragma unroll
            for (int mt = 0; mt < 4; mt++) {
                uint32_t off = (uint32_t)((a_row + mt * 16) * 128) + kt * 32 + a_cb;
                off = SWZ128(off);
                ldsm_x4(ah[mt], st + OFF_A + off);
            }
            uint32_t bh[4][2];
#pragma unroll
            for (int p = 0; p < 2; p++) {
                uint32_t off = (uint32_t)((b_row0 + p * 16) * 128) + kt * 32 + b_cb;
                off = SWZ128(off);
                uint32_t r[4];
                ldsm_x4(r, st + OFF_B + off);
                bh[2 * p][0] = r[0]; bh[2 * p][1] = r[1];
                bh[2 * p + 1][0] = r[2]; bh[2 * p + 1][1] = r[3];
            }
#pragma unroll
            for (int mt = 0; mt < 4; mt++)
#pragma unroll
                for (int nt = 0; nt < 4; nt++)
                    mma_f16(acc[mt][nt], ah[mt], bh[nt]);
        }
        __syncthreads();
    }

    // epilogue
#pragma unroll
    for (int nt = 0; nt < 4; nt++) {
        int c0 = n0 + wn * 32 + nt * 8 + (lid & 3) * 2;
        float b0 = bias[c0], b1 = bias[c0 + 1];
#pragma unroll
        for (int mt = 0; mt < 4; mt++) {
            int r0 = m0 + wm * 64 + mt * 16 + (lid >> 2);
            float v0 = (acc[mt][nt][0] + b0) * oscl, v1 = (acc[mt][nt][1] + b1) * oscl;
            float v2 = (acc[mt][nt][2] + b0) * oscl, v3 = (acc[mt][nt][3] + b1) * oscl;
            if (MODE == 0) {
                *(uint32_t*)&Cq[(size_t)r0 * Dd + c0] = pkh2(v0, v1);
                *(uint32_t*)&Cq[(size_t)(r0 + 8) * Dd + c0] = pkh2(v2, v3);
            } else {
                float2 w0 = {v0, v1}, w1 = {v2, v3};
                *(float2*)&C[(size_t)r0 * Dd + c0] = w0;
                *(float2*)&C[(size_t)(r0 + 8) * Dd + c0] = w1;
            }
        }
    }
}

// ================= Flash attention (all-fp16, 512 threads, 256 query rows) =====
// 16 warps/CTA (4/SMSP) for latency hiding; 3-stage BKV=128 pipeline with one
// barrier per tile; global heavy-first; ex2.approx.f16x2 softmax; ones-MMA lsum.
constexpr int AT_STG = 32768;                      // K 16KB | V 16KB
constexpr int A_QZ = 3 * AT_STG;                   // Q 32K (reused for out staging)
constexpr int ATT_SMEM = A_QZ + 32768 + 1024;      // ~130KB

template<bool MASK>
__device__ __forceinline__ void attn_tile(
    uint32_t st, int kv0, int r0g, int r1g, int lid,
    int krow, uint32_t kcb, int vrow, uint32_t vcb,
    const uint32_t (&qh)[4][4],
    float (&o)[8][4], float (&lsc)[4])
{
    const uint32_t ONESB[2] = {0x3C003C00u, 0x3C003C00u};   // fp16 1.0 x4
#pragma unroll
    for (int hf = 0; hf < 4; hf++) {
        // S = Q K^T over 32 keys (already in log2 domain via pre-scaled Q)
        float s[4][4];
#pragma unroll
        for (int nt = 0; nt < 4; nt++)
#pragma unroll
            for (int e = 0; e < 4; e++) s[nt][e] = 0.f;
#pragma unroll
        for (int kd = 0; kd < 4; kd++) {
#pragma unroll
            for (int np = 0; np < 2; np++) {
                uint32_t off = SWZ128((uint32_t)((hf * 32 + np * 16 + krow) * 128) + kd * 32 + kcb);
                uint32_t kh_[4];
                ldsm_x4(kh_, st + off);            // K fp16
                mma_f16(s[2 * np],     qh[kd], kh_);
                mma_f16(s[2 * np + 1], qh[kd], kh_ + 2);
            }
        }

        // P = 2^s via half2 EX2
        uint32_t pa[2][4];
#pragma unroll
        for (int nt = 0; nt < 4; nt++) {
            float v0 = s[nt][0], v1 = s[nt][1], v2 = s[nt][2], v3 = s[nt][3];
            if (MASK) {
                int kg = kv0 + hf * 32 + nt * 8 + (lid & 3) * 2;
                v0 = (kg     <= r0g) ? v0 : -INFINITY;
                v1 = (kg + 1 <= r0g) ? v1 : -INFINITY;
                v2 = (kg     <= r1g) ? v2 : -INFINITY;
                v3 = (kg + 1 <= r1g) ? v3 : -INFINITY;
            }
            int kp = nt >> 1, e = (nt & 1) * 2;
            pa[kp][e]     = ex2_h2(pkh2(v0, v1));
            pa[kp][e + 1] = ex2_h2(pkh2(v2, v3));
        }

        // lsum += P @ ones  (exact fp32 row sums)
        mma_f16(lsc, pa[0], ONESB);
        mma_f16(lsc, pa[1], ONESB);

        // O += P V over this 32-key half
#pragma unroll
        for (int kp = 0; kp < 2; kp++) {
#pragma unroll
            for (int np = 0; np < 4; np++) {
                uint32_t off = SWZ128((uint32_t)((hf * 32 + kp * 16 + vrow) * 128) + np * 32 + vcb);
                uint32_t vh_[4];
                ldsm_x4_t(vh_, st + 16384 + off);  // V fp16
                mma_f16(o[2 * np],     pa[kp], vh_);
                mma_f16(o[2 * np + 1], pa[kp], vh_ + 2);
            }
        }
    }
}

__global__ __launch_bounds__(512, 1) void attn_mma()
{
    extern __shared__ char smc[];
    uint32_t sraw = smem_u32(smc);
    uint32_t sb = (sraw + 1023u) & ~1023u;
    char* smb = smc + (sb - sraw);

    const int tid = threadIdx.x, lid = tid & 31, wq = tid >> 5;   // 16 warps
    // global heavy-first 1-D grid: bids 0..31 are the heaviest (qi=7) CTAs
    const int qi = 7 - ((int)blockIdx.x >> 5);    // 0..7 (256 query rows each)
    const int bh = (int)blockIdx.x & 31;
    const int b = bh >> 4, h = bh & 15;
    const int q0 = qi * 256;
    const size_t base2 = ((size_t)b * Ss * Dd + (size_t)h * DH) * 2;   // bytes

    // Q load: fp16, 256 rows x 128B
#pragma unroll
    for (int i = 0; i < 4; i++) {
        int idx = tid + i * 512;
        int row = idx >> 3; uint32_t colb = (uint32_t)((idx & 7) * 16);
        const char* src = (const char*)g_q16 + base2 + (size_t)(q0 + row) * 2048 + colb;
        cp16(sb + A_QZ + SWZ128((uint32_t)(row * 128) + colb), src);
    }
    CP_COMMIT();

    const char* kvb[2] = {(const char*)g_k16, (const char*)g_v16};
    auto kvload = [&](int kt) {
        uint32_t st = sb + (kt % 3) * AT_STG;
        int kv0 = kt * 128;
#pragma unroll
        for (int i = 0; i < 4; i++) {
            int idx = tid + i * 512;
            int arr = idx >> 10, c = idx & 1023;
            int row = c >> 3; uint32_t colb = (uint32_t)((c & 7) * 16);
            cp16(st + arr * 16384 + SWZ128((uint32_t)(row * 128) + colb),
                 kvb[arr] + base2 + (size_t)(kv0 + row) * 2048 + colb);
        }
    };

    const int nkt = 2 * qi + 2;   // 128-key tiles (>= 2 always)
    kvload(0); CP_COMMIT();
    kvload(1); CP_COMMIT();
    CP_WAIT(2);          // Q done
    __syncthreads();

    // Q fragments -> registers (4 dim-chunks of 16)
    uint32_t qh[4][4];
    {
        const int a_row = wq * 16 + (lid & 15);
        const uint32_t a_cb = (uint32_t)(((lid >> 4) & 1) * 16);
#pragma unroll
        for (int kd = 0; kd < 4; kd++)
            ldsm_x4(qh[kd], sb + A_QZ + SWZ128((uint32_t)(a_row * 128) + kd * 32 + a_cb));
    }

    float o[8][4];
#pragma unroll
    for (int nt = 0; nt < 8; nt++)
#pragma unroll
        for (int e = 0; e < 4; e++) o[nt][e] = 0.f;
    float lsc[4] = {0.f, 0.f, 0.f, 0.f};

    const int r0g = q0 + wq * 16 + (lid >> 2);
    const int r1g = r0g + 8;
    const int mg = lid >> 3;
    const int krow = (mg >> 1) * 8 + (lid & 7);
    const uint32_t kcb = (uint32_t)((mg & 1) * 16);
    const int vrow = lid & 15;
    const uint32_t vcb = (uint32_t)((lid >> 4) * 16);

    const int ktfull = 2 * qi;    // tiles [0, ktfull) need no mask (last two masked)
    for (int kt = 0; kt < nkt; kt++) {
        if (kt + 1 < nkt) { CP_WAIT(1); } else { CP_WAIT(0); }
        __syncthreads();          // stage kt ready; all reads of stage (kt-1)%3 done
        if (kt + 2 < nkt) { kvload(kt + 2); CP_COMMIT(); }   // safe: targets (kt-1)%3
        uint32_t st = sb + (kt % 3) * AT_STG;
        if (kt < ktfull)
            attn_tile<false>(st, kt * 128, r0g, r1g, lid, krow, kcb, vrow, vcb,
                             qh, o, lsc);
        else
            attn_tile<true>(st, kt * 128, r0g, r1g, lid, krow, kcb, vrow, vcb,
                            qh, o, lsc);
    }

    // row sums straight from the ones-MMA accumulator
    float il0 = 1.f / lsc[0], il1 = 1.f / lsc[2];

    // epilogue: normalize, fp16, stage in smem, coalesced store
    __syncthreads();              // all tile reads done before overwriting Q region
    {
        int rs0 = wq * 16 + (lid >> 2);
#pragma unroll
        for (int nt = 0; nt < 8; nt++) {
            uint32_t colb = (uint32_t)(nt * 16 + (lid & 3) * 4);
            *(uint32_t*)(smb + A_QZ + rs0 * 128 + colb)       = pkh2(o[nt][0] * il0, o[nt][1] * il0);
            *(uint32_t*)(smb + A_QZ + (rs0 + 8) * 128 + colb) = pkh2(o[nt][2] * il1, o[nt][3] * il1);
        }
    }
    __syncthreads();
#pragma unroll
    for (int i = 0; i < 4; i++) {
        int idx = tid + i * 512;
        int row = idx >> 3; uint32_t colb = (uint32_t)((idx & 7) * 16);
        uint4 v = *(uint4*)(smb + A_QZ + row * 128 + colb);
        char* dst = (char*)g_a16 + base2 + (size_t)(q0 + row) * 2048 + colb;
        *(uint4*)dst = v;
    }
}

// ---------------- launch ----------------
extern "C" void kernel_launch(void* const* d_in, const int* in_sizes, int n_in,
                              void* d_out, int out_size)
{
    const float* x  = (const float*)d_in[0];
    const float* Wq = (const float*)d_in[1];
    const float* bq = (const float*)d_in[2];
    const float* Wk = (const float*)d_in[3];
    const float* bk = (const float*)d_in[4];
    const float* Wv = (const float*)d_in[5];
    const float* bv = (const float*)d_in[6];
    const float* Wo = (const float*)d_in[7];
    const float* bo = (const float*)d_in[8];
    float* out = (float*)d_out;

    __half *x16, *wt16;
    cudaGetSymbolAddress((void**)&x16,  g_x16);
    cudaGetSymbolAddress((void**)&wt16, g_wt16);

    cudaFuncSetAttribute(gemm_mma<0>,
                         cudaFuncAttributeMaxDynamicSharedMemorySize, GEMM_SMEM);
    cudaFuncSetAttribute(gemm_mma<1>,
                         cudaFuncAttributeMaxDynamicSharedMemorySize, GEMM_SMEM);
    cudaFuncSetAttribute(attn_mma,
                         cudaFuncAttributeMaxDynamicSharedMemorySize, ATT_SMEM);

    // fused prep: z 0..3 = transpose Wq/Wk/Wv/Wo, z 4..7 = x fp32->fp16 slices
    prep_all<<<dim3(32, 32, 8), 256>>>(x, Wq, Wk, Wv, Wo, x16, wt16);

    // Fused QKV projection: one launch, outputs routed to q16(scaled)/k16/v16
    gemm_mma<0><<<dim3(24, MM / BM), 256, GEMM_SMEM>>>(bq, bk, bv, nullptr);

    // 256 CTAs x 512 threads, 256 query rows each, global heavy-first
    attn_mma<<<256, 512, ATT_SMEM>>>();

    // Output projection
    gemm_mma<1><<<dim3(8, MM / BM), 256, GEMM_SMEM>>>(bo, nullptr, nullptr, out);
}